// round 2
// baseline (speedup 1.0000x reference)
#include <cuda_runtime.h>
#include <cstddef>

// ---------------- problem dims ----------------
#define BS 4096
#define IN 2056
#define MF 24
#define H 4
#define HE 128
#define E 64
#define NA 128
#define RNN 256
#define ENT 127           // 64 enemies + 63 allies
#define KTOT 8192         // E*NA

// ---------------- scratch (device globals; no allocs allowed) ----------------
__device__ float g_hid[BS * 192];          // relu(obs@[Wb1;Wh1]^T + bias)
__device__ float g_bt[BS];                 // b_term
__device__ float g_wh[BS * H];             // |w_head|
__device__ float g_h1[BS * 1536];          // relu hidden of q/km/vm MLPs
__device__ float g_q[BS * H * E];
__device__ float g_km[BS * H * E];
__device__ float g_vm[BS * H * E];
__device__ float g_te[BS * H * 16];        // (Wke^T q)/8
__device__ float g_ta[BS * H * 16];        // (Wka^T q)/8
__device__ float g_l0[BS * H];             // (q.km)/8
__device__ float g_S[RNN];                 // row-sums of Wf
__device__ float g_dmixed[(size_t)BS * KTOT];  // mixed minus b_term

// =====================================================================
// K1: front GEMM  C[4096,192] = relu(obs @ [Wb1;Wh1]^T + [bb1;bh1])
// =====================================================================
__global__ __launch_bounds__(256) void k_front(const float* __restrict__ obs,
                                               const float* __restrict__ Wb1,
                                               const float* __restrict__ bb1,
                                               const float* __restrict__ Wh1,
                                               const float* __restrict__ bh1) {
    __shared__ float As[8][64];
    __shared__ float Bs[8][65];
    int bm = blockIdx.x * 64;
    int bn = blockIdx.y * 64;
    int tid = threadIdx.x;
    int tx = tid & 15, ty = tid >> 4;
    float acc[4][4] = {};
    for (int k0 = 0; k0 < IN; k0 += 8) {
        #pragma unroll
        for (int i = tid; i < 512; i += 256) {
            int r = i >> 3, c = i & 7;
            As[c][r] = obs[(size_t)(bm + r) * IN + k0 + c];
        }
        #pragma unroll
        for (int i = tid; i < 512; i += 256) {
            int r = i >> 3, c = i & 7;
            int n = bn + r;
            const float* W = (n < 64) ? (Wb1 + (size_t)n * IN) : (Wh1 + (size_t)(n - 64) * IN);
            Bs[c][r] = W[k0 + c];
        }
        __syncthreads();
        #pragma unroll
        for (int k = 0; k < 8; k++) {
            float a[4], b[4];
            #pragma unroll
            for (int i = 0; i < 4; i++) a[i] = As[k][ty * 4 + i];
            #pragma unroll
            for (int j = 0; j < 4; j++) b[j] = Bs[k][tx * 4 + j];
            #pragma unroll
            for (int i = 0; i < 4; i++)
                #pragma unroll
                for (int j = 0; j < 4; j++) acc[i][j] += a[i] * b[j];
        }
        __syncthreads();
    }
    #pragma unroll
    for (int i = 0; i < 4; i++)
        #pragma unroll
        for (int j = 0; j < 4; j++) {
            int r = bm + ty * 4 + i, n = bn + tx * 4 + j;
            float bias = (n < 64) ? bb1[n] : bh1[n - 64];
            g_hid[r * 192 + n] = fmaxf(acc[i][j] + bias, 0.f);
        }
}

// =====================================================================
// K2: b_term + w_head from hid
// =====================================================================
__global__ __launch_bounds__(256) void k_post_front(const float* __restrict__ Wb2,
                                                    const float* __restrict__ bb2,
                                                    const float* __restrict__ Wh2,
                                                    const float* __restrict__ bh2) {
    int warp = threadIdx.x >> 5, lane = threadIdx.x & 31;
    int b = blockIdx.x * 8 + warp;
    const float* hrow = g_hid + b * 192;
    float s = hrow[lane] * Wb2[lane] + hrow[32 + lane] * Wb2[32 + lane];
    #pragma unroll
    for (int o = 16; o; o >>= 1) s += __shfl_xor_sync(0xffffffffu, s, o);
    if (lane == 0) g_bt[b] = s + bb2[0];
    #pragma unroll
    for (int h = 0; h < H; h++) {
        float t = 0.f;
        #pragma unroll
        for (int j = lane; j < HE; j += 32) t += hrow[64 + j] * Wh2[h * HE + j];
        #pragma unroll
        for (int o = 16; o; o >>= 1) t += __shfl_xor_sync(0xffffffffu, t, o);
        if (lane == 0) g_wh[b * H + h] = fabsf(t + bh2[h]);
    }
}

// =====================================================================
// K3a: h1[4096,1536] = relu(m @ W1^T + b1) for q/km/vm stacked
// =====================================================================
__global__ __launch_bounds__(256) void k_h1(const float* __restrict__ obs,
                                            const float* __restrict__ Wq1, const float* __restrict__ bq1,
                                            const float* __restrict__ Wkm1, const float* __restrict__ bkm1,
                                            const float* __restrict__ Wvm1, const float* __restrict__ bvm1) {
    __shared__ float Ms[64][25];
    __shared__ float Ws[64][25];
    int bm = blockIdx.x * 64, bn = blockIdx.y * 64;
    int tid = threadIdx.x;
    for (int i = tid; i < 64 * 24; i += 256) {
        int r = i / 24, f = i % 24;
        int col = (f < 4) ? f : (2032 + f);
        Ms[r][f] = obs[(size_t)(bm + r) * IN + col];
    }
    for (int i = tid; i < 64 * 24; i += 256) {
        int r = i / 24, f = i % 24;
        int n = bn + r;
        int mlp = n >> 9;
        int idx = n & 511;
        const float* W = (mlp == 0) ? Wq1 : (mlp == 1) ? Wkm1 : Wvm1;
        Ws[r][f] = W[idx * 24 + f];
    }
    __syncthreads();
    int tx = tid & 15, ty = tid >> 4;
    float acc[4][4] = {};
    #pragma unroll
    for (int k = 0; k < 24; k++) {
        float a[4], b[4];
        #pragma unroll
        for (int i = 0; i < 4; i++) a[i] = Ms[ty * 4 + i][k];
        #pragma unroll
        for (int j = 0; j < 4; j++) b[j] = Ws[tx * 4 + j][k];
        #pragma unroll
        for (int i = 0; i < 4; i++)
            #pragma unroll
            for (int j = 0; j < 4; j++) acc[i][j] += a[i] * b[j];
    }
    #pragma unroll
    for (int i = 0; i < 4; i++)
        #pragma unroll
        for (int j = 0; j < 4; j++) {
            int r = bm + ty * 4 + i, n = bn + tx * 4 + j;
            int mlp = n >> 9, idx = n & 511;
            const float* bias = (mlp == 0) ? bq1 : (mlp == 1) ? bkm1 : bvm1;
            g_h1[r * 1536 + n] = fmaxf(acc[i][j] + bias[idx], 0.f);
        }
}

// =====================================================================
// K3b: second layer (per head, no bias): q/km/vm [4096, H, E]
// =====================================================================
__global__ __launch_bounds__(256) void k_qkv(const float* __restrict__ Wq2,
                                             const float* __restrict__ Wkm2,
                                             const float* __restrict__ Wvm2) {
    __shared__ float As[16][65];
    __shared__ float Bs[16][65];
    int bm = blockIdx.x * 64;
    int mlp = blockIdx.y >> 2, h = blockIdx.y & 3;
    const float* W2 = ((mlp == 0) ? Wq2 : (mlp == 1) ? Wkm2 : Wvm2) + h * E * HE;
    float* out = (mlp == 0) ? g_q : (mlp == 1) ? g_km : g_vm;
    int colbase = mlp * 512 + h * HE;
    int tid = threadIdx.x, tx = tid & 15, ty = tid >> 4;
    float acc[4][4] = {};
    for (int k0 = 0; k0 < HE; k0 += 16) {
        for (int i = tid; i < 1024; i += 256) {
            int r = i >> 4, k = i & 15;
            As[k][r] = g_h1[(bm + r) * 1536 + colbase + k0 + k];
        }
        for (int i = tid; i < 1024; i += 256) {
            int e = i >> 4, k = i & 15;
            Bs[k][e] = W2[e * HE + k0 + k];
        }
        __syncthreads();
        #pragma unroll
        for (int k = 0; k < 16; k++) {
            float a[4], b[4];
            #pragma unroll
            for (int i = 0; i < 4; i++) a[i] = As[k][ty * 4 + i];
            #pragma unroll
            for (int j = 0; j < 4; j++) b[j] = Bs[k][tx * 4 + j];
            #pragma unroll
            for (int i = 0; i < 4; i++)
                #pragma unroll
                for (int j = 0; j < 4; j++) acc[i][j] += a[i] * b[j];
        }
        __syncthreads();
    }
    #pragma unroll
    for (int i = 0; i < 4; i++)
        #pragma unroll
        for (int j = 0; j < 4; j++) {
            int bb = bm + ty * 4 + i, e = tx * 4 + j;
            out[bb * (H * E) + h * E + e] = acc[i][j];
        }
}

// =====================================================================
// K3c: fold keys into query: te/ta = (q^T Wk)/8, l0 = (q.km)/8
// =====================================================================
__global__ __launch_bounds__(128) void k_fold(const float* __restrict__ Wke,
                                              const float* __restrict__ Wka) {
    int b = blockIdx.x;
    __shared__ float qs[256], kms[256];
    int tid = threadIdx.x;
    qs[tid] = g_q[b * 256 + tid];
    qs[tid + 128] = g_q[b * 256 + 128 + tid];
    kms[tid] = g_km[b * 256 + tid];
    kms[tid + 128] = g_km[b * 256 + 128 + tid];
    __syncthreads();
    {
        int h = (tid & 63) >> 4, d = tid & 15;
        const float* Wk = (tid < 64) ? Wke : Wka;
        float s = 0.f;
        #pragma unroll
        for (int e = 0; e < 64; e++) s += qs[h * 64 + e] * Wk[h * 1024 + e * 16 + d];
        s *= 0.125f;
        if (tid < 64) g_te[b * 64 + h * 16 + d] = s;
        else          g_ta[b * 64 + h * 16 + d] = s;
    }
    int w = tid >> 5, lane = tid & 31;
    float s = qs[w * 64 + lane] * kms[w * 64 + lane] +
              qs[w * 64 + 32 + lane] * kms[w * 64 + 32 + lane];
    #pragma unroll
    for (int o = 16; o; o >>= 1) s += __shfl_xor_sync(0xffffffffu, s, o);
    if (lane == 0) g_l0[b * 4 + w] = s * 0.125f;
}

// =====================================================================
// K4: per-batch fused attention + mix -> dmixed (WITHOUT b_term)
// =====================================================================
__global__ __launch_bounds__(256) void k_attn(const float* __restrict__ obs,
                                              const float* __restrict__ Wve,
                                              const float* __restrict__ Wva) {
    extern __shared__ float sm[];
    float* ent = sm;            // 2032
    float* Wv  = sm + 2032;     // 8192 : [sel][h][e][d]
    float* lg  = Wv + 8192;     // 512  : [h][na]
    float* u   = lg + 512;      // 512
    float* vms = u + 512;       // 256
    float* tv  = vms + 256;     // 128  : te then ta
    float* whl = tv + 128;      // 8    : wh[4], l0[4]
    float* mix = whl + 8;       // 8192 : [e][na]
    int b = blockIdx.x, tid = threadIdx.x;

    const float* orow = obs + (size_t)b * IN;
    for (int i = tid; i < 2032; i += 256) ent[i] = orow[4 + i];
    for (int i = tid; i < 4096; i += 256) { Wv[i] = Wve[i]; Wv[4096 + i] = Wva[i]; }
    for (int i = tid; i < 256; i += 256) vms[i] = g_vm[b * 256 + i];
    if (tid < 64) { tv[tid] = g_te[b * 64 + tid]; tv[64 + tid] = g_ta[b * 64 + tid]; }
    if (tid < 8) whl[tid] = (tid < 4) ? g_wh[b * 4 + tid] : g_l0[b * 4 + (tid - 4)];
    __syncthreads();

    // entity logits: 4 heads x 127 entities, dot over 16 dims
    for (int i = tid; i < 508; i += 256) {
        int h = i / 127, n = i - h * 127;
        const float* tp = tv + ((n < 64) ? 0 : 64) + h * 16;
        const float* ep = ent + n * 16;
        float s = 0.f;
        #pragma unroll
        for (int d = 0; d < 16; d++) s += ep[d] * tp[d];
        lg[h * 128 + 1 + n] = s;
    }
    if (tid < 4) lg[tid * 128] = whl[4 + tid];
    __syncthreads();

    // softmax per head, scaled by w_head -> u
    if (tid < 128) {
        int h = tid >> 5, lane = tid & 31;
        float v0[4], m0 = -3.4e38f;
        #pragma unroll
        for (int j = 0; j < 4; j++) { v0[j] = lg[h * 128 + lane + 32 * j]; m0 = fmaxf(m0, v0[j]); }
        #pragma unroll
        for (int o = 16; o; o >>= 1) m0 = fmaxf(m0, __shfl_xor_sync(0xffffffffu, m0, o));
        float ss = 0.f;
        #pragma unroll
        for (int j = 0; j < 4; j++) { v0[j] = expf(v0[j] - m0); ss += v0[j]; }
        #pragma unroll
        for (int o = 16; o; o >>= 1) ss += __shfl_xor_sync(0xffffffffu, ss, o);
        float sc = whl[h] / ss;
        #pragma unroll
        for (int j = 0; j < 4; j++) u[h * 128 + lane + 32 * j] = v0[j] * sc;
    }
    __syncthreads();

    // mixed[e][na] = sum_h u[h][na] * v[h][na][e]   (v computed on the fly)
    {
        int na = tid & 127, half = tid >> 7;
        float uh[4];
        #pragma unroll
        for (int h = 0; h < 4; h++) uh[h] = u[h * 128 + na];
        int e0 = half * 32;
        if (na == 0) {
            for (int e = e0; e < e0 + 32; e++) {
                float s = 0.f;
                #pragma unroll
                for (int h = 0; h < 4; h++) s += uh[h] * vms[h * 64 + e];
                mix[e * 128] = s;
            }
        } else {
            int n = na - 1;
            const float4* ep4 = (const float4*)(ent + n * 16);
            float4 e0v = ep4[0], e1v = ep4[1], e2v = ep4[2], e3v = ep4[3];
            const float* Wvb = Wv + ((n < 64) ? 0 : 4096);
            for (int e = e0; e < e0 + 32; e++) {
                float s = 0.f;
                #pragma unroll
                for (int h = 0; h < 4; h++) {
                    const float4* wp = (const float4*)(Wvb + h * 1024 + e * 16);
                    float4 w0 = wp[0], w1 = wp[1], w2 = wp[2], w3 = wp[3];
                    float vhe = e0v.x * w0.x + e0v.y * w0.y + e0v.z * w0.z + e0v.w * w0.w
                              + e1v.x * w1.x + e1v.y * w1.y + e1v.z * w1.z + e1v.w * w1.w
                              + e2v.x * w2.x + e2v.y * w2.y + e2v.z * w2.z + e2v.w * w2.w
                              + e3v.x * w3.x + e3v.y * w3.y + e3v.z * w3.z + e3v.w * w3.w;
                    s += uh[h] * vhe;
                }
                mix[e * 128 + na] = s;
            }
        }
    }
    __syncthreads();
    float* outp = g_dmixed + (size_t)b * KTOT;
    for (int i = tid; i < KTOT; i += 256) outp[i] = mix[i];
}

// =====================================================================
// K4b: S[r] = sum_k Wf[r,k]
// =====================================================================
__global__ __launch_bounds__(256) void k_S(const float* __restrict__ Wf) {
    int r = blockIdx.x;
    float s = 0.f;
    for (int i = threadIdx.x; i < KTOT; i += 256) s += Wf[(size_t)r * KTOT + i];
    __shared__ float red[256];
    red[threadIdx.x] = s;
    __syncthreads();
    for (int o = 128; o; o >>= 1) {
        if (threadIdx.x < o) red[threadIdx.x] += red[threadIdx.x + o];
        __syncthreads();
    }
    if (threadIdx.x == 0) g_S[r] = red[0];
}

// =====================================================================
// K5: out[4096,256] = dmixed @ Wf^T + b_term*S + bf
// =====================================================================
__global__ __launch_bounds__(256) void k_final(const float* __restrict__ Wf,
                                               const float* __restrict__ bf,
                                               float* __restrict__ out) {
    __shared__ float As[16][65];
    __shared__ float Bs[16][65];
    int bm = blockIdx.x * 64, bn = blockIdx.y * 64;
    int tid = threadIdx.x, tx = tid & 15, ty = tid >> 4;
    float acc[4][4] = {};
    for (int k0 = 0; k0 < KTOT; k0 += 16) {
        for (int i = tid; i < 1024; i += 256) {
            int r = i >> 4, k = i & 15;
            As[k][r] = g_dmixed[(size_t)(bm + r) * KTOT + k0 + k];
        }
        for (int i = tid; i < 1024; i += 256) {
            int n = i >> 4, k = i & 15;
            Bs[k][n] = Wf[(size_t)(bn + n) * KTOT + k0 + k];
        }
        __syncthreads();
        #pragma unroll
        for (int k = 0; k < 16; k++) {
            float a[4], b[4];
            #pragma unroll
            for (int i = 0; i < 4; i++) a[i] = As[k][ty * 4 + i];
            #pragma unroll
            for (int j = 0; j < 4; j++) b[j] = Bs[k][tx * 4 + j];
            #pragma unroll
            for (int i = 0; i < 4; i++)
                #pragma unroll
                for (int j = 0; j < 4; j++) acc[i][j] += a[i] * b[j];
        }
        __syncthreads();
    }
    #pragma unroll
    for (int i = 0; i < 4; i++)
        #pragma unroll
        for (int j = 0; j < 4; j++) {
            int r = bm + ty * 4 + i, n = bn + tx * 4 + j;
            out[r * RNN + n] = acc[i][j] + g_bt[r] * g_S[n] + bf[n];
        }
}

// =====================================================================
// launch
// =====================================================================
extern "C" void kernel_launch(void* const* d_in, const int* in_sizes, int n_in,
                              void* d_out, int out_size) {
    const float* obs  = (const float*)d_in[0];
    const float* Wq1  = (const float*)d_in[1];
    const float* bq1  = (const float*)d_in[2];
    const float* Wq2  = (const float*)d_in[3];
    const float* Wkm1 = (const float*)d_in[4];
    const float* bkm1 = (const float*)d_in[5];
    const float* Wkm2 = (const float*)d_in[6];
    const float* Wke  = (const float*)d_in[7];
    const float* Wka  = (const float*)d_in[8];
    const float* Wvm1 = (const float*)d_in[9];
    const float* bvm1 = (const float*)d_in[10];
    const float* Wvm2 = (const float*)d_in[11];
    const float* Wve  = (const float*)d_in[12];
    const float* Wva  = (const float*)d_in[13];
    const float* Wb1  = (const float*)d_in[14];
    const float* bb1  = (const float*)d_in[15];
    const float* Wb2  = (const float*)d_in[16];
    const float* bb2  = (const float*)d_in[17];
    const float* Wh1  = (const float*)d_in[18];
    const float* bh1  = (const float*)d_in[19];
    const float* Wh2  = (const float*)d_in[20];
    const float* bh2  = (const float*)d_in[21];
    const float* Wf   = (const float*)d_in[22];
    const float* bf   = (const float*)d_in[23];
    float* out = (float*)d_out;

    const int attn_smem = (2032 + 8192 + 512 + 512 + 256 + 128 + 8 + 8192) * 4;
    cudaFuncSetAttribute(k_attn, cudaFuncAttributeMaxDynamicSharedMemorySize, attn_smem);

    k_S<<<RNN, 256>>>(Wf);
    k_front<<<dim3(64, 3), 256>>>(obs, Wb1, bb1, Wh1, bh1);
    k_post_front<<<512, 256>>>(Wb2, bb2, Wh2, bh2);
    k_h1<<<dim3(64, 24), 256>>>(obs, Wq1, bq1, Wkm1, bkm1, Wvm1, bvm1);
    k_qkv<<<dim3(64, 12), 256>>>(Wq2, Wkm2, Wvm2);
    k_fold<<<4096, 128>>>(Wke, Wka);
    k_attn<<<4096, 256, attn_smem>>>(obs, Wve, Wva);
    k_final<<<dim3(64, 4), 256>>>(Wf, bf, out);
}

// round 4
// speedup vs baseline: 3.3825x; 3.3825x over previous
#include <cuda_runtime.h>
#include <cuda_bf16.h>
#include <cstdint>
#include <cstddef>

// ---------------- problem dims ----------------
#define BS 4096
#define IN 2056
#define MF 24
#define H 4
#define HE 128
#define E 64
#define NA 128
#define RNN 256
#define KTOT 8192         // E*NA

// ---------------- scratch (device globals; no allocs allowed) ----------------
__device__ float g_hid[BS * 192];
__device__ float g_bt[BS];
__device__ float g_wh[BS * H];
__device__ float g_h1[BS * 1536];
__device__ float g_q[BS * H * E];
__device__ float g_km[BS * H * E];
__device__ float g_vm[BS * H * E];
__device__ float g_te[BS * H * 16];
__device__ float g_ta[BS * H * 16];
__device__ float g_l0[BS * H];
__device__ float g_S[RNN];
__device__ __align__(16) __nv_bfloat16 g_Abf[(size_t)BS * KTOT];   // dmixed (minus b_term) in bf16
__device__ __align__(16) __nv_bfloat16 g_Wfbf[(size_t)RNN * KTOT]; // Wf in bf16

// ---------------- PTX helpers (sm_80-era: mma.sync / ldmatrix / cp.async) ----
__device__ __forceinline__ uint32_t smem_u32(const void* p) {
    uint32_t a;
    asm("{ .reg .u64 t; cvta.to.shared.u64 t, %1; cvt.u32.u64 %0, t; }" : "=r"(a) : "l"(p));
    return a;
}
__device__ __forceinline__ void cp16(uint32_t dst, const void* src) {
    asm volatile("cp.async.cg.shared.global [%0], [%1], 16;" :: "r"(dst), "l"(src) : "memory");
}
#define CP_COMMIT() asm volatile("cp.async.commit_group;" ::: "memory")
#define CP_WAIT(n)  asm volatile("cp.async.wait_group %0;" :: "n"(n) : "memory")

#define LDSM_X4(r0, r1, r2, r3, addr) \
    asm volatile("ldmatrix.sync.aligned.m8n8.x4.shared.b16 {%0,%1,%2,%3}, [%4];" \
                 : "=r"(r0), "=r"(r1), "=r"(r2), "=r"(r3) : "r"(addr))

#define MMA16816(d, a, b) \
    asm volatile("mma.sync.aligned.m16n8k16.row.col.f32.bf16.bf16.f32 " \
                 "{%0,%1,%2,%3}, {%4,%5,%6,%7}, {%8,%9}, {%0,%1,%2,%3};" \
                 : "+f"((d)[0]), "+f"((d)[1]), "+f"((d)[2]), "+f"((d)[3]) \
                 : "r"((a)[0]), "r"((a)[1]), "r"((a)[2]), "r"((a)[3]), \
                   "r"((b)[0]), "r"((b)[1]))

#define SWZ(x) ((x) ^ (((x) >> 3) & 0x70))

// =====================================================================
// K1: front GEMM  C[4096,192] = relu(obs @ [Wb1;Wh1]^T + [bb1;bh1])  (fp32)
// =====================================================================
__global__ __launch_bounds__(256) void k_front(const float* __restrict__ obs,
                                               const float* __restrict__ Wb1,
                                               const float* __restrict__ bb1,
                                               const float* __restrict__ Wh1,
                                               const float* __restrict__ bh1) {
    __shared__ float As[8][64];
    __shared__ float Bs[8][65];
    int bm = blockIdx.x * 64;
    int bn = blockIdx.y * 64;
    int tid = threadIdx.x;
    int tx = tid & 15, ty = tid >> 4;
    float acc[4][4] = {};
    for (int k0 = 0; k0 < IN; k0 += 8) {
        #pragma unroll
        for (int i = tid; i < 512; i += 256) {
            int r = i >> 3, c = i & 7;
            As[c][r] = obs[(size_t)(bm + r) * IN + k0 + c];
        }
        #pragma unroll
        for (int i = tid; i < 512; i += 256) {
            int r = i >> 3, c = i & 7;
            int n = bn + r;
            const float* W = (n < 64) ? (Wb1 + (size_t)n * IN) : (Wh1 + (size_t)(n - 64) * IN);
            Bs[c][r] = W[k0 + c];
        }
        __syncthreads();
        #pragma unroll
        for (int k = 0; k < 8; k++) {
            float a[4], b[4];
            #pragma unroll
            for (int i = 0; i < 4; i++) a[i] = As[k][ty * 4 + i];
            #pragma unroll
            for (int j = 0; j < 4; j++) b[j] = Bs[k][tx * 4 + j];
            #pragma unroll
            for (int i = 0; i < 4; i++)
                #pragma unroll
                for (int j = 0; j < 4; j++) acc[i][j] += a[i] * b[j];
        }
        __syncthreads();
    }
    #pragma unroll
    for (int i = 0; i < 4; i++)
        #pragma unroll
        for (int j = 0; j < 4; j++) {
            int r = bm + ty * 4 + i, n = bn + tx * 4 + j;
            float bias = (n < 64) ? bb1[n] : bh1[n - 64];
            g_hid[r * 192 + n] = fmaxf(acc[i][j] + bias, 0.f);
        }
}

// =====================================================================
// K2: b_term + w_head from hid
// =====================================================================
__global__ __launch_bounds__(256) void k_post_front(const float* __restrict__ Wb2,
                                                    const float* __restrict__ bb2,
                                                    const float* __restrict__ Wh2,
                                                    const float* __restrict__ bh2) {
    int warp = threadIdx.x >> 5, lane = threadIdx.x & 31;
    int b = blockIdx.x * 8 + warp;
    const float* hrow = g_hid + b * 192;
    float s = hrow[lane] * Wb2[lane] + hrow[32 + lane] * Wb2[32 + lane];
    #pragma unroll
    for (int o = 16; o; o >>= 1) s += __shfl_xor_sync(0xffffffffu, s, o);
    if (lane == 0) g_bt[b] = s + bb2[0];
    #pragma unroll
    for (int h = 0; h < H; h++) {
        float t = 0.f;
        #pragma unroll
        for (int j = lane; j < HE; j += 32) t += hrow[64 + j] * Wh2[h * HE + j];
        #pragma unroll
        for (int o = 16; o; o >>= 1) t += __shfl_xor_sync(0xffffffffu, t, o);
        if (lane == 0) g_wh[b * H + h] = fabsf(t + bh2[h]);
    }
}

// =====================================================================
// K3a: h1[4096,1536] = relu(m @ W1^T + b1) for q/km/vm stacked
// =====================================================================
__global__ __launch_bounds__(256) void k_h1(const float* __restrict__ obs,
                                            const float* __restrict__ Wq1, const float* __restrict__ bq1,
                                            const float* __restrict__ Wkm1, const float* __restrict__ bkm1,
                                            const float* __restrict__ Wvm1, const float* __restrict__ bvm1) {
    __shared__ float Ms[64][25];
    __shared__ float Ws[64][25];
    int bm = blockIdx.x * 64, bn = blockIdx.y * 64;
    int tid = threadIdx.x;
    for (int i = tid; i < 64 * 24; i += 256) {
        int r = i / 24, f = i % 24;
        int col = (f < 4) ? f : (2032 + f);
        Ms[r][f] = obs[(size_t)(bm + r) * IN + col];
    }
    for (int i = tid; i < 64 * 24; i += 256) {
        int r = i / 24, f = i % 24;
        int n = bn + r;
        int mlp = n >> 9;
        int idx = n & 511;
        const float* W = (mlp == 0) ? Wq1 : (mlp == 1) ? Wkm1 : Wvm1;
        Ws[r][f] = W[idx * 24 + f];
    }
    __syncthreads();
    int tx = tid & 15, ty = tid >> 4;
    float acc[4][4] = {};
    #pragma unroll
    for (int k = 0; k < 24; k++) {
        float a[4], b[4];
        #pragma unroll
        for (int i = 0; i < 4; i++) a[i] = Ms[ty * 4 + i][k];
        #pragma unroll
        for (int j = 0; j < 4; j++) b[j] = Ws[tx * 4 + j][k];
        #pragma unroll
        for (int i = 0; i < 4; i++)
            #pragma unroll
            for (int j = 0; j < 4; j++) acc[i][j] += a[i] * b[j];
    }
    #pragma unroll
    for (int i = 0; i < 4; i++)
        #pragma unroll
        for (int j = 0; j < 4; j++) {
            int r = bm + ty * 4 + i, n = bn + tx * 4 + j;
            int mlp = n >> 9, idx = n & 511;
            const float* bias = (mlp == 0) ? bq1 : (mlp == 1) ? bkm1 : bvm1;
            g_h1[r * 1536 + n] = fmaxf(acc[i][j] + bias[idx], 0.f);
        }
}

// =====================================================================
// K3b: second layer (per head, no bias): q/km/vm [4096, H, E]
// =====================================================================
__global__ __launch_bounds__(256) void k_qkv(const float* __restrict__ Wq2,
                                             const float* __restrict__ Wkm2,
                                             const float* __restrict__ Wvm2) {
    __shared__ float As[16][65];
    __shared__ float Bs[16][65];
    int bm = blockIdx.x * 64;
    int mlp = blockIdx.y >> 2, h = blockIdx.y & 3;
    const float* W2 = ((mlp == 0) ? Wq2 : (mlp == 1) ? Wkm2 : Wvm2) + h * E * HE;
    float* out = (mlp == 0) ? g_q : (mlp == 1) ? g_km : g_vm;
    int colbase = mlp * 512 + h * HE;
    int tid = threadIdx.x, tx = tid & 15, ty = tid >> 4;
    float acc[4][4] = {};
    for (int k0 = 0; k0 < HE; k0 += 16) {
        for (int i = tid; i < 1024; i += 256) {
            int r = i >> 4, k = i & 15;
            As[k][r] = g_h1[(bm + r) * 1536 + colbase + k0 + k];
        }
        for (int i = tid; i < 1024; i += 256) {
            int e = i >> 4, k = i & 15;
            Bs[k][e] = W2[e * HE + k0 + k];
        }
        __syncthreads();
        #pragma unroll
        for (int k = 0; k < 16; k++) {
            float a[4], b[4];
            #pragma unroll
            for (int i = 0; i < 4; i++) a[i] = As[k][ty * 4 + i];
            #pragma unroll
            for (int j = 0; j < 4; j++) b[j] = Bs[k][tx * 4 + j];
            #pragma unroll
            for (int i = 0; i < 4; i++)
                #pragma unroll
                for (int j = 0; j < 4; j++) acc[i][j] += a[i] * b[j];
        }
        __syncthreads();
    }
    #pragma unroll
    for (int i = 0; i < 4; i++)
        #pragma unroll
        for (int j = 0; j < 4; j++) {
            int bb = bm + ty * 4 + i, e = tx * 4 + j;
            out[bb * (H * E) + h * E + e] = acc[i][j];
        }
}

// =====================================================================
// K3c: fold keys into query: te/ta = (q^T Wk)/8, l0 = (q.km)/8
// =====================================================================
__global__ __launch_bounds__(128) void k_fold(const float* __restrict__ Wke,
                                              const float* __restrict__ Wka) {
    int b = blockIdx.x;
    __shared__ float qs[256], kms[256];
    int tid = threadIdx.x;
    qs[tid] = g_q[b * 256 + tid];
    qs[tid + 128] = g_q[b * 256 + 128 + tid];
    kms[tid] = g_km[b * 256 + tid];
    kms[tid + 128] = g_km[b * 256 + 128 + tid];
    __syncthreads();
    {
        int h = (tid & 63) >> 4, d = tid & 15;
        const float* Wk = (tid < 64) ? Wke : Wka;
        float s = 0.f;
        #pragma unroll
        for (int e = 0; e < 64; e++) s += qs[h * 64 + e] * Wk[h * 1024 + e * 16 + d];
        s *= 0.125f;
        if (tid < 64) g_te[b * 64 + h * 16 + d] = s;
        else          g_ta[b * 64 + h * 16 + d] = s;
    }
    int w = tid >> 5, lane = tid & 31;
    float s = qs[w * 64 + lane] * kms[w * 64 + lane] +
              qs[w * 64 + 32 + lane] * kms[w * 64 + 32 + lane];
    #pragma unroll
    for (int o = 16; o; o >>= 1) s += __shfl_xor_sync(0xffffffffu, s, o);
    if (lane == 0) g_l0[b * 4 + w] = s * 0.125f;
}

// =====================================================================
// K4: per-batch fused attention + mix -> g_Abf (bf16, WITHOUT b_term)
// =====================================================================
__global__ __launch_bounds__(256) void k_attn(const float* __restrict__ obs,
                                              const float* __restrict__ Wve,
                                              const float* __restrict__ Wva) {
    extern __shared__ float sm[];
    float* ent = sm;            // 2032
    float* Wv  = sm + 2032;     // 8192 : [sel][h][e][d]
    float* lg  = Wv + 8192;     // 512  : [h][na]
    float* u   = lg + 512;      // 512
    float* vms = u + 512;       // 256
    float* tv  = vms + 256;     // 128
    float* whl = tv + 128;      // 8
    int b = blockIdx.x, tid = threadIdx.x;

    const float* orow = obs + (size_t)b * IN;
    for (int i = tid; i < 2032; i += 256) ent[i] = orow[4 + i];
    for (int i = tid; i < 4096; i += 256) { Wv[i] = Wve[i]; Wv[4096 + i] = Wva[i]; }
    for (int i = tid; i < 256; i += 256) vms[i] = g_vm[b * 256 + i];
    if (tid < 64) { tv[tid] = g_te[b * 64 + tid]; tv[64 + tid] = g_ta[b * 64 + tid]; }
    if (tid < 8) whl[tid] = (tid < 4) ? g_wh[b * 4 + tid] : g_l0[b * 4 + (tid - 4)];
    __syncthreads();

    // entity logits
    for (int i = tid; i < 508; i += 256) {
        int h = i / 127, n = i - h * 127;
        const float* tp = tv + ((n < 64) ? 0 : 64) + h * 16;
        const float* ep = ent + n * 16;
        float s = 0.f;
        #pragma unroll
        for (int d = 0; d < 16; d++) s += ep[d] * tp[d];
        lg[h * 128 + 1 + n] = s;
    }
    if (tid < 4) lg[tid * 128] = whl[4 + tid];
    __syncthreads();

    // softmax per head, scaled by w_head -> u
    if (tid < 128) {
        int h = tid >> 5, lane = tid & 31;
        float v0[4], m0 = -3.4e38f;
        #pragma unroll
        for (int j = 0; j < 4; j++) { v0[j] = lg[h * 128 + lane + 32 * j]; m0 = fmaxf(m0, v0[j]); }
        #pragma unroll
        for (int o = 16; o; o >>= 1) m0 = fmaxf(m0, __shfl_xor_sync(0xffffffffu, m0, o));
        float ss = 0.f;
        #pragma unroll
        for (int j = 0; j < 4; j++) { v0[j] = expf(v0[j] - m0); ss += v0[j]; }
        #pragma unroll
        for (int o = 16; o; o >>= 1) ss += __shfl_xor_sync(0xffffffffu, ss, o);
        float sc = whl[h] / ss;
        #pragma unroll
        for (int j = 0; j < 4; j++) u[h * 128 + lane + 32 * j] = v0[j] * sc;
    }
    __syncthreads();

    // mixed[e][na] = sum_h u[h][na] * v[h][na][e] -> direct bf16 store (coalesced over na)
    {
        __nv_bfloat16* arow = g_Abf + (size_t)b * KTOT;
        int na = tid & 127, half = tid >> 7;
        float uh[4];
        #pragma unroll
        for (int h = 0; h < 4; h++) uh[h] = u[h * 128 + na];
        int e0 = half * 32;
        if (na == 0) {
            for (int e = e0; e < e0 + 32; e++) {
                float s = 0.f;
                #pragma unroll
                for (int h = 0; h < 4; h++) s += uh[h] * vms[h * 64 + e];
                arow[e * 128] = __float2bfloat16_rn(s);
            }
        } else {
            int n = na - 1;
            const float4* ep4 = (const float4*)(ent + n * 16);
            float4 e0v = ep4[0], e1v = ep4[1], e2v = ep4[2], e3v = ep4[3];
            const float* Wvb = Wv + ((n < 64) ? 0 : 4096);
            for (int e = e0; e < e0 + 32; e++) {
                float s = 0.f;
                #pragma unroll
                for (int h = 0; h < 4; h++) {
                    const float4* wp = (const float4*)(Wvb + h * 1024 + e * 16);
                    float4 w0 = wp[0], w1 = wp[1], w2 = wp[2], w3 = wp[3];
                    float vhe = e0v.x * w0.x + e0v.y * w0.y + e0v.z * w0.z + e0v.w * w0.w
                              + e1v.x * w1.x + e1v.y * w1.y + e1v.z * w1.z + e1v.w * w1.w
                              + e2v.x * w2.x + e2v.y * w2.y + e2v.z * w2.z + e2v.w * w2.w
                              + e3v.x * w3.x + e3v.y * w3.y + e3v.z * w3.z + e3v.w * w3.w;
                    s += uh[h] * vhe;
                }
                arow[e * 128 + na] = __float2bfloat16_rn(s);
            }
        }
    }
}

// =====================================================================
// K4b: S[r] = sum_k Wf[r,k]  (fp32, rank-1 term precision-critical)
// =====================================================================
__global__ __launch_bounds__(256) void k_S(const float* __restrict__ Wf) {
    int r = blockIdx.x;
    float s = 0.f;
    for (int i = threadIdx.x; i < KTOT; i += 256) s += Wf[(size_t)r * KTOT + i];
    __shared__ float red[256];
    red[threadIdx.x] = s;
    __syncthreads();
    for (int o = 128; o; o >>= 1) {
        if (threadIdx.x < o) red[threadIdx.x] += red[threadIdx.x + o];
        __syncthreads();
    }
    if (threadIdx.x == 0) g_S[r] = red[0];
}

// =====================================================================
// K4c: convert Wf -> bf16
// =====================================================================
__global__ __launch_bounds__(256) void k_wf2bf(const float* __restrict__ Wf) {
    size_t i = (size_t)blockIdx.x * 256 + threadIdx.x;   // grid 2048 -> 524288 float4s
    float4 v = ((const float4*)Wf)[i];
    __nv_bfloat162* dst = (__nv_bfloat162*)g_Wfbf;
    dst[2 * i]     = __floats2bfloat162_rn(v.x, v.y);
    dst[2 * i + 1] = __floats2bfloat162_rn(v.z, v.w);
}

// =====================================================================
// K5: bf16 mma.sync GEMM: out[4096,256] = Abf @ Wfbf^T + bt*S + bf
//     CTA tile M=64 x N=128, 8 warps (2x4), warp tile 32x32,
//     K-chunks of 64, double-buffered cp.async, SW128 + ldmatrix.
// =====================================================================
__global__ __launch_bounds__(256) void k_final_mma(const float* __restrict__ bfv,
                                                   float* __restrict__ out) {
    __shared__ __align__(128) char sm8[49152];
    const uint32_t sb = smem_u32(sm8);
    const int tid = threadIdx.x, lane = tid & 31, w = tid >> 5;
    const int bm = blockIdx.x * 64, bn = blockIdx.y * 128;
    const int wm = (w & 1) * 32, wn = (w >> 1) * 32;
    const uint32_t Aoff[2] = {0u, 8192u};
    const uint32_t Boff[2] = {16384u, 32768u};

    float d[2][4][4] = {};   // [m-tile 16][n-tile 8][frag]

    // ---- chunk loader: A 64x64 bf16, B 128x64 bf16, SW128 swizzled ----
    auto loadChunk = [&](int t, int buf) {
        const __nv_bfloat16* Asrc = g_Abf + (size_t)bm * KTOT + (size_t)t * 64;
        #pragma unroll
        for (int i = 0; i < 2; i++) {
            int idx = tid + 256 * i;
            int row = idx >> 3, c = idx & 7;
            cp16(sb + Aoff[buf] + SWZ((uint32_t)(row * 128 + c * 16)),
                 Asrc + (size_t)row * KTOT + c * 8);
        }
        const __nv_bfloat16* Bsrc = g_Wfbf + (size_t)bn * KTOT + (size_t)t * 64;
        #pragma unroll
        for (int i = 0; i < 4; i++) {
            int idx = tid + 256 * i;
            int row = idx >> 3, c = idx & 7;
            cp16(sb + Boff[buf] + SWZ((uint32_t)(row * 128 + c * 16)),
                 Bsrc + (size_t)row * KTOT + c * 8);
        }
        CP_COMMIT();
    };

    loadChunk(0, 0);
    for (int t = 0; t < 128; t++) {
        const int buf = t & 1;
        if (t + 1 < 128) { loadChunk(t + 1, buf ^ 1); CP_WAIT(1); }
        else             { CP_WAIT(0); }
        __syncthreads();

        const uint32_t abase = sb + Aoff[buf];
        const uint32_t bbase = sb + Boff[buf];
        #pragma unroll
        for (int ks = 0; ks < 4; ks++) {
            uint32_t a[2][4], b[4][2];
            #pragma unroll
            for (int mt = 0; mt < 2; mt++) {
                uint32_t byte = (uint32_t)((wm + mt * 16 + (lane & 15)) * 128
                                           + (lane >> 4) * 16 + ks * 32);
                LDSM_X4(a[mt][0], a[mt][1], a[mt][2], a[mt][3], abase + SWZ(byte));
            }
            #pragma unroll
            for (int nr = 0; nr < 2; nr++) {
                uint32_t byte = (uint32_t)((wn + nr * 16 + (lane & 15)) * 128
                                           + (lane >> 4) * 16 + ks * 32);
                uint32_t r0, r1, r2, r3;
                LDSM_X4(r0, r1, r2, r3, bbase + SWZ(byte));
                b[nr * 2 + 0][0] = r0; b[nr * 2 + 0][1] = r2;
                b[nr * 2 + 1][0] = r1; b[nr * 2 + 1][1] = r3;
            }
            #pragma unroll
            for (int mt = 0; mt < 2; mt++)
                #pragma unroll
                for (int nt = 0; nt < 4; nt++)
                    MMA16816(d[mt][nt], a[mt], b[nt]);
        }
        __syncthreads();
    }

    // ---- epilogue: + b_term*S + bf ----
    const int nbase = bn + wn + (lane & 3) * 2;
    #pragma unroll
    for (int mt = 0; mt < 2; mt++) {
        #pragma unroll
        for (int half = 0; half < 2; half++) {
            int row = bm + wm + mt * 16 + half * 8 + (lane >> 2);
            float btv = g_bt[row];
            #pragma unroll
            for (int nt = 0; nt < 4; nt++) {
                int col = nbase + nt * 8;
                float v0 = d[mt][nt][half * 2 + 0] + btv * g_S[col]     + bfv[col];
                float v1 = d[mt][nt][half * 2 + 1] + btv * g_S[col + 1] + bfv[col + 1];
                *(float2*)&out[(size_t)row * RNN + col] = make_float2(v0, v1);
            }
        }
    }
}

// =====================================================================
// launch
// =====================================================================
extern "C" void kernel_launch(void* const* d_in, const int* in_sizes, int n_in,
                              void* d_out, int out_size) {
    const float* obs  = (const float*)d_in[0];
    const float* Wq1  = (const float*)d_in[1];
    const float* bq1  = (const float*)d_in[2];
    const float* Wq2  = (const float*)d_in[3];
    const float* Wkm1 = (const float*)d_in[4];
    const float* bkm1 = (const float*)d_in[5];
    const float* Wkm2 = (const float*)d_in[6];
    const float* Wke  = (const float*)d_in[7];
    const float* Wka  = (const float*)d_in[8];
    const float* Wvm1 = (const float*)d_in[9];
    const float* bvm1 = (const float*)d_in[10];
    const float* Wvm2 = (const float*)d_in[11];
    const float* Wve  = (const float*)d_in[12];
    const float* Wva  = (const float*)d_in[13];
    const float* Wb1  = (const float*)d_in[14];
    const float* bb1  = (const float*)d_in[15];
    const float* Wb2  = (const float*)d_in[16];
    const float* bb2  = (const float*)d_in[17];
    const float* Wh1  = (const float*)d_in[18];
    const float* bh1  = (const float*)d_in[19];
    const float* Wh2  = (const float*)d_in[20];
    const float* bh2  = (const float*)d_in[21];
    const float* Wf   = (const float*)d_in[22];
    const float* bf   = (const float*)d_in[23];
    float* out = (float*)d_out;

    const int attn_smem = (2032 + 8192 + 512 + 512 + 256 + 128 + 8) * 4;   // 46560
    cudaFuncSetAttribute(k_attn, cudaFuncAttributeMaxDynamicSharedMemorySize, attn_smem);

    k_wf2bf<<<2048, 256>>>(Wf);
    k_S<<<RNN, 256>>>(Wf);
    k_front<<<dim3(64, 3), 256>>>(obs, Wb1, bb1, Wh1, bh1);
    k_post_front<<<512, 256>>>(Wb2, bb2, Wh2, bh2);
    k_h1<<<dim3(64, 24), 256>>>(obs, Wq1, bq1, Wkm1, bkm1, Wvm1, bvm1);
    k_qkv<<<dim3(64, 12), 256>>>(Wq2, Wkm2, Wvm2);
    k_fold<<<4096, 128>>>(Wke, Wka);
    k_attn<<<4096, 256, attn_smem>>>(obs, Wve, Wva);
    k_final_mma<<<dim3(64, 2), 256>>>(bf, out);
}

// round 5
// speedup vs baseline: 4.3681x; 1.2914x over previous
#include <cuda_runtime.h>
#include <cuda_bf16.h>
#include <cstdint>
#include <cstddef>

// ---------------- problem dims ----------------
#define BS 4096
#define IN 2056
#define MF 24
#define H 4
#define HE 128
#define E 64
#define NA 128
#define RNN 256
#define KTOT 8192         // E*NA

// ---------------- scratch (device globals; no allocs allowed) ----------------
__device__ float g_hid[BS * 192];
__device__ float g_bt[BS];
__device__ float g_wh[BS * H];
__device__ float g_h1[BS * 1536];
__device__ float g_q[BS * H * E];
__device__ float g_km[BS * H * E];
__device__ float g_vm[BS * H * E];
__device__ float g_te[BS * H * 16];
__device__ float g_ta[BS * H * 16];
__device__ float g_l0[BS * H];
__device__ float g_S[RNN];
// A matrix for final GEMM, layout [b][na*64+e]  (PERMUTED k-index!)
__device__ __align__(16) __nv_bfloat16 g_Abf[(size_t)BS * KTOT];
// Wf in bf16, same permuted layout: g_Wfbf[r][na*64+e] = Wf[r][e*128+na]
__device__ __align__(16) __nv_bfloat16 g_Wfbf[(size_t)RNN * KTOT];
// flattened value weights: [sel(0=enemy,1=ally)][e][h*16+d]
__device__ __align__(16) __nv_bfloat16 g_Wvbf[2 * 64 * 64];

// ---------------- PTX helpers (sm_80-era: mma.sync / ldmatrix / cp.async) ----
__device__ __forceinline__ uint32_t smem_u32(const void* p) {
    uint32_t a;
    asm("{ .reg .u64 t; cvta.to.shared.u64 t, %1; cvt.u32.u64 %0, t; }" : "=r"(a) : "l"(p));
    return a;
}
__device__ __forceinline__ void cp16(uint32_t dst, const void* src) {
    asm volatile("cp.async.cg.shared.global [%0], [%1], 16;" :: "r"(dst), "l"(src) : "memory");
}
#define CP_COMMIT() asm volatile("cp.async.commit_group;" ::: "memory")
#define CP_WAIT(n)  asm volatile("cp.async.wait_group %0;" :: "n"(n) : "memory")

#define LDSM_X4(r0, r1, r2, r3, addr) \
    asm volatile("ldmatrix.sync.aligned.m8n8.x4.shared.b16 {%0,%1,%2,%3}, [%4];" \
                 : "=r"(r0), "=r"(r1), "=r"(r2), "=r"(r3) : "r"(addr))

#define MMA16816(d, a, b) \
    asm volatile("mma.sync.aligned.m16n8k16.row.col.f32.bf16.bf16.f32 " \
                 "{%0,%1,%2,%3}, {%4,%5,%6,%7}, {%8,%9}, {%0,%1,%2,%3};" \
                 : "+f"((d)[0]), "+f"((d)[1]), "+f"((d)[2]), "+f"((d)[3]) \
                 : "r"((a)[0]), "r"((a)[1]), "r"((a)[2]), "r"((a)[3]), \
                   "r"((b)[0]), "r"((b)[1]))

#define SWZ(x) ((x) ^ (((x) >> 3) & 0x70))

// =====================================================================
// K0: prep — blocks 0..255: permute+convert Wf row r -> g_Wfbf, compute S[r]
//           block 256: flatten Wve/Wva -> g_Wvbf
// =====================================================================
__global__ __launch_bounds__(256) void k_prep(const float* __restrict__ Wf,
                                              const float* __restrict__ Wve,
                                              const float* __restrict__ Wva) {
    int r = blockIdx.x;
    if (r < 256) {
        __shared__ float row[8256];   // 8192 + 64 pad (1 per 128)
        __shared__ float red[8];
        int tid = threadIdx.x;
        float s = 0.f;
        for (int i = tid; i < 8192; i += 256) {
            float v = Wf[(size_t)r * 8192 + i];
            row[i + (i >> 7)] = v;
            s += v;
        }
        #pragma unroll
        for (int o = 16; o; o >>= 1) s += __shfl_xor_sync(0xffffffffu, s, o);
        if ((tid & 31) == 0) red[tid >> 5] = s;
        __syncthreads();
        if (tid == 0) {
            float t = 0.f;
            #pragma unroll
            for (int j = 0; j < 8; j++) t += red[j];
            g_S[r] = t;
        }
        for (int i = tid; i < 8192; i += 256) {
            int na = i >> 6, e = i & 63;
            int src = e * 128 + na;
            g_Wfbf[(size_t)r * 8192 + i] = __float2bfloat16_rn(row[src + (src >> 7)]);
        }
    } else {
        for (int i = threadIdx.x; i < 8192; i += 256) {
            int sel = i >> 12, j = i & 4095;
            int e = j >> 6, hd = j & 63, h = hd >> 4, d = hd & 15;
            const float* W = sel ? Wva : Wve;
            g_Wvbf[i] = __float2bfloat16_rn(W[h * 1024 + e * 16 + d]);
        }
    }
}

// =====================================================================
// K1: front GEMM  C[4096,192] = relu(obs @ [Wb1;Wh1]^T + [bb1;bh1])  (fp32)
// =====================================================================
__global__ __launch_bounds__(256) void k_front(const float* __restrict__ obs,
                                               const float* __restrict__ Wb1,
                                               const float* __restrict__ bb1,
                                               const float* __restrict__ Wh1,
                                               const float* __restrict__ bh1) {
    __shared__ float As[8][64];
    __shared__ float Bs[8][65];
    int bm = blockIdx.x * 64;
    int bn = blockIdx.y * 64;
    int tid = threadIdx.x;
    int tx = tid & 15, ty = tid >> 4;
    float acc[4][4] = {};
    for (int k0 = 0; k0 < IN; k0 += 8) {
        #pragma unroll
        for (int i = tid; i < 512; i += 256) {
            int r = i >> 3, c = i & 7;
            As[c][r] = obs[(size_t)(bm + r) * IN + k0 + c];
        }
        #pragma unroll
        for (int i = tid; i < 512; i += 256) {
            int r = i >> 3, c = i & 7;
            int n = bn + r;
            const float* W = (n < 64) ? (Wb1 + (size_t)n * IN) : (Wh1 + (size_t)(n - 64) * IN);
            Bs[c][r] = W[k0 + c];
        }
        __syncthreads();
        #pragma unroll
        for (int k = 0; k < 8; k++) {
            float a[4], b[4];
            #pragma unroll
            for (int i = 0; i < 4; i++) a[i] = As[k][ty * 4 + i];
            #pragma unroll
            for (int j = 0; j < 4; j++) b[j] = Bs[k][tx * 4 + j];
            #pragma unroll
            for (int i = 0; i < 4; i++)
                #pragma unroll
                for (int j = 0; j < 4; j++) acc[i][j] += a[i] * b[j];
        }
        __syncthreads();
    }
    #pragma unroll
    for (int i = 0; i < 4; i++)
        #pragma unroll
        for (int j = 0; j < 4; j++) {
            int r = bm + ty * 4 + i, n = bn + tx * 4 + j;
            float bias = (n < 64) ? bb1[n] : bh1[n - 64];
            g_hid[r * 192 + n] = fmaxf(acc[i][j] + bias, 0.f);
        }
}

// =====================================================================
// K2: b_term + w_head from hid
// =====================================================================
__global__ __launch_bounds__(256) void k_post_front(const float* __restrict__ Wb2,
                                                    const float* __restrict__ bb2,
                                                    const float* __restrict__ Wh2,
                                                    const float* __restrict__ bh2) {
    int warp = threadIdx.x >> 5, lane = threadIdx.x & 31;
    int b = blockIdx.x * 8 + warp;
    const float* hrow = g_hid + b * 192;
    float s = hrow[lane] * Wb2[lane] + hrow[32 + lane] * Wb2[32 + lane];
    #pragma unroll
    for (int o = 16; o; o >>= 1) s += __shfl_xor_sync(0xffffffffu, s, o);
    if (lane == 0) g_bt[b] = s + bb2[0];
    #pragma unroll
    for (int h = 0; h < H; h++) {
        float t = 0.f;
        #pragma unroll
        for (int j = lane; j < HE; j += 32) t += hrow[64 + j] * Wh2[h * HE + j];
        #pragma unroll
        for (int o = 16; o; o >>= 1) t += __shfl_xor_sync(0xffffffffu, t, o);
        if (lane == 0) g_wh[b * H + h] = fabsf(t + bh2[h]);
    }
}

// =====================================================================
// K3a: h1[4096,1536] = relu(m @ W1^T + b1) for q/km/vm stacked
// =====================================================================
__global__ __launch_bounds__(256) void k_h1(const float* __restrict__ obs,
                                            const float* __restrict__ Wq1, const float* __restrict__ bq1,
                                            const float* __restrict__ Wkm1, const float* __restrict__ bkm1,
                                            const float* __restrict__ Wvm1, const float* __restrict__ bvm1) {
    __shared__ float Ms[64][25];
    __shared__ float Ws[64][25];
    int bm = blockIdx.x * 64, bn = blockIdx.y * 64;
    int tid = threadIdx.x;
    for (int i = tid; i < 64 * 24; i += 256) {
        int r = i / 24, f = i % 24;
        int col = (f < 4) ? f : (2032 + f);
        Ms[r][f] = obs[(size_t)(bm + r) * IN + col];
    }
    for (int i = tid; i < 64 * 24; i += 256) {
        int r = i / 24, f = i % 24;
        int n = bn + r;
        int mlp = n >> 9;
        int idx = n & 511;
        const float* W = (mlp == 0) ? Wq1 : (mlp == 1) ? Wkm1 : Wvm1;
        Ws[r][f] = W[idx * 24 + f];
    }
    __syncthreads();
    int tx = tid & 15, ty = tid >> 4;
    float acc[4][4] = {};
    #pragma unroll
    for (int k = 0; k < 24; k++) {
        float a[4], b[4];
        #pragma unroll
        for (int i = 0; i < 4; i++) a[i] = Ms[ty * 4 + i][k];
        #pragma unroll
        for (int j = 0; j < 4; j++) b[j] = Ws[tx * 4 + j][k];
        #pragma unroll
        for (int i = 0; i < 4; i++)
            #pragma unroll
            for (int j = 0; j < 4; j++) acc[i][j] += a[i] * b[j];
    }
    #pragma unroll
    for (int i = 0; i < 4; i++)
        #pragma unroll
        for (int j = 0; j < 4; j++) {
            int r = bm + ty * 4 + i, n = bn + tx * 4 + j;
            int mlp = n >> 9, idx = n & 511;
            const float* bias = (mlp == 0) ? bq1 : (mlp == 1) ? bkm1 : bvm1;
            g_h1[r * 1536 + n] = fmaxf(acc[i][j] + bias[idx], 0.f);
        }
}

// =====================================================================
// K3b: second layer (per head, no bias): q/km/vm [4096, H, E]
// =====================================================================
__global__ __launch_bounds__(256) void k_qkv(const float* __restrict__ Wq2,
                                             const float* __restrict__ Wkm2,
                                             const float* __restrict__ Wvm2) {
    __shared__ float As[16][65];
    __shared__ float Bs[16][65];
    int bm = blockIdx.x * 64;
    int mlp = blockIdx.y >> 2, h = blockIdx.y & 3;
    const float* W2 = ((mlp == 0) ? Wq2 : (mlp == 1) ? Wkm2 : Wvm2) + h * E * HE;
    float* out = (mlp == 0) ? g_q : (mlp == 1) ? g_km : g_vm;
    int colbase = mlp * 512 + h * HE;
    int tid = threadIdx.x, tx = tid & 15, ty = tid >> 4;
    float acc[4][4] = {};
    for (int k0 = 0; k0 < HE; k0 += 16) {
        for (int i = tid; i < 1024; i += 256) {
            int r = i >> 4, k = i & 15;
            As[k][r] = g_h1[(bm + r) * 1536 + colbase + k0 + k];
        }
        for (int i = tid; i < 1024; i += 256) {
            int e = i >> 4, k = i & 15;
            Bs[k][e] = W2[e * HE + k0 + k];
        }
        __syncthreads();
        #pragma unroll
        for (int k = 0; k < 16; k++) {
            float a[4], b[4];
            #pragma unroll
            for (int i = 0; i < 4; i++) a[i] = As[k][ty * 4 + i];
            #pragma unroll
            for (int j = 0; j < 4; j++) b[j] = Bs[k][tx * 4 + j];
            #pragma unroll
            for (int i = 0; i < 4; i++)
                #pragma unroll
                for (int j = 0; j < 4; j++) acc[i][j] += a[i] * b[j];
        }
        __syncthreads();
    }
    #pragma unroll
    for (int i = 0; i < 4; i++)
        #pragma unroll
        for (int j = 0; j < 4; j++) {
            int bb = bm + ty * 4 + i, e = tx * 4 + j;
            out[bb * (H * E) + h * E + e] = acc[i][j];
        }
}

// =====================================================================
// K3c: fold keys into query: te/ta = (q^T Wk)/8, l0 = (q.km)/8
// =====================================================================
__global__ __launch_bounds__(128) void k_fold(const float* __restrict__ Wke,
                                              const float* __restrict__ Wka) {
    int b = blockIdx.x;
    __shared__ float qs[256], kms[256];
    int tid = threadIdx.x;
    qs[tid] = g_q[b * 256 + tid];
    qs[tid + 128] = g_q[b * 256 + 128 + tid];
    kms[tid] = g_km[b * 256 + tid];
    kms[tid + 128] = g_km[b * 256 + 128 + tid];
    __syncthreads();
    {
        int h = (tid & 63) >> 4, d = tid & 15;
        const float* Wk = (tid < 64) ? Wke : Wka;
        float s = 0.f;
        #pragma unroll
        for (int e = 0; e < 64; e++) s += qs[h * 64 + e] * Wk[h * 1024 + e * 16 + d];
        s *= 0.125f;
        if (tid < 64) g_te[b * 64 + h * 16 + d] = s;
        else          g_ta[b * 64 + h * 16 + d] = s;
    }
    int w = tid >> 5, lane = tid & 31;
    float s = qs[w * 64 + lane] * kms[w * 64 + lane] +
              qs[w * 64 + 32 + lane] * kms[w * 64 + 32 + lane];
    #pragma unroll
    for (int o = 16; o; o >>= 1) s += __shfl_xor_sync(0xffffffffu, s, o);
    if (lane == 0) g_l0[b * 4 + w] = s * 0.125f;
}

// =====================================================================
// K4: per-batch attention: logits + softmax + Z = u (x) ent, then
//     tensor-core mix: A[b][na][e] = Z[127x64] @ WvFlat[64x64] (enemy/ally)
// =====================================================================
__global__ __launch_bounds__(256) void k_attn(const float* __restrict__ obs) {
    __shared__ float ent[2032];
    __shared__ float lg[512];
    __shared__ float u[512];
    __shared__ float vms[256];
    __shared__ float tv[128];
    __shared__ float whl[8];
    __shared__ __align__(128) __nv_bfloat16 Zs[128 * 64];   // [n][hd], SW128
    __shared__ __align__(128) __nv_bfloat16 Wvs[128 * 64];  // rows 0-63 Wve, 64-127 Wva, SW128

    int b = blockIdx.x, tid = threadIdx.x;
    char* ZsB = (char*)Zs;
    char* WvsB = (char*)Wvs;

    const float* orow = obs + (size_t)b * IN;
    for (int i = tid; i < 2032; i += 256) ent[i] = orow[4 + i];
    // Wv flat (bf16, 16 KB) -> smem, SW128-swizzled rows of 128 B
    {
        const uint4* wsrc = (const uint4*)g_Wvbf;
        #pragma unroll
        for (int i = tid; i < 1024; i += 256) {
            int row = i >> 3, c = i & 7;
            *(uint4*)(WvsB + SWZ((uint32_t)(row * 128 + c * 16))) = wsrc[i];
        }
    }
    vms[tid & 255] = g_vm[b * 256 + (tid & 255)];
    if (tid < 64) { tv[tid] = g_te[b * 64 + tid]; tv[64 + tid] = g_ta[b * 64 + tid]; }
    if (tid < 8) whl[tid] = (tid < 4) ? g_wh[b * 4 + tid] : g_l0[b * 4 + (tid - 4)];
    __syncthreads();

    // entity logits
    for (int i = tid; i < 508; i += 256) {
        int h = i / 127, n = i - h * 127;
        const float* tp = tv + ((n < 64) ? 0 : 64) + h * 16;
        const float* ep = ent + n * 16;
        float s = 0.f;
        #pragma unroll
        for (int d = 0; d < 16; d++) s += ep[d] * tp[d];
        lg[h * 128 + 1 + n] = s;
    }
    if (tid < 4) lg[tid * 128] = whl[4 + tid];
    __syncthreads();

    // softmax per head, scaled by w_head -> u
    if (tid < 128) {
        int h = tid >> 5, lane = tid & 31;
        float v0[4], m0 = -3.4e38f;
        #pragma unroll
        for (int j = 0; j < 4; j++) { v0[j] = lg[h * 128 + lane + 32 * j]; m0 = fmaxf(m0, v0[j]); }
        #pragma unroll
        for (int o = 16; o; o >>= 1) m0 = fmaxf(m0, __shfl_xor_sync(0xffffffffu, m0, o));
        float ss = 0.f;
        #pragma unroll
        for (int j = 0; j < 4; j++) { v0[j] = expf(v0[j] - m0); ss += v0[j]; }
        #pragma unroll
        for (int o = 16; o; o >>= 1) ss += __shfl_xor_sync(0xffffffffu, ss, o);
        float sc = whl[h] / ss;
        #pragma unroll
        for (int j = 0; j < 4; j++) u[h * 128 + lane + 32 * j] = v0[j] * sc;
    }
    __syncthreads();

    // build Z[n][hd] = u[h][n+1] * ent[n*16+d]  (bf16, SW128); row 127 = 0
    #pragma unroll
    for (int i = tid; i < 8192; i += 256) {
        int n = i >> 6, hd = i & 63;
        float val = 0.f;
        if (n < 127) {
            int h = hd >> 4, d = hd & 15;
            val = u[h * 128 + n + 1] * ent[n * 16 + d];
        }
        *(__nv_bfloat16*)(ZsB + SWZ((uint32_t)(n * 128 + hd * 2))) = __float2bfloat16_rn(val);
    }
    // A row na=0: sum_h u[h][0] * vms[h][e]
    __nv_bfloat16* arow = g_Abf + (size_t)b * KTOT;
    if (tid < 64) {
        float s = 0.f;
        #pragma unroll
        for (int h = 0; h < 4; h++) s += u[h * 128] * vms[h * 64 + tid];
        arow[tid] = __float2bfloat16_rn(s);
    }
    __syncthreads();

    // mma: warps 0-3 -> enemy rows 0..63 (B = Wve rows 0..63),
    //      warps 4-7 -> ally rows 64..127 (B = Wva rows 64..127)
    {
        int w = tid >> 5, lane = tid & 31;
        int sel = w >> 2;
        int mbase = w * 16;
        uint32_t zb = smem_u32(Zs);
        uint32_t wb = smem_u32(Wvs) + (uint32_t)sel * 8192u;
        float d[8][4] = {};
        #pragma unroll
        for (int ks = 0; ks < 4; ks++) {
            uint32_t a[4];
            uint32_t byte = (uint32_t)((mbase + (lane & 15)) * 128 + (lane >> 4) * 16 + ks * 32);
            LDSM_X4(a[0], a[1], a[2], a[3], zb + SWZ(byte));
            uint32_t bfr[8][2];
            #pragma unroll
            for (int nr = 0; nr < 4; nr++) {
                uint32_t byte2 = (uint32_t)((nr * 16 + (lane & 15)) * 128 + (lane >> 4) * 16 + ks * 32);
                uint32_t r0, r1, r2, r3;
                LDSM_X4(r0, r1, r2, r3, wb + SWZ(byte2));
                bfr[nr * 2 + 0][0] = r0; bfr[nr * 2 + 0][1] = r2;
                bfr[nr * 2 + 1][0] = r1; bfr[nr * 2 + 1][1] = r3;
            }
            #pragma unroll
            for (int nt = 0; nt < 8; nt++) MMA16816(d[nt], a, bfr[nt]);
        }
        // epilogue: A[b][na][e] = result, na = Zrow+1 (skip Zrow 127)
        #pragma unroll
        for (int half = 0; half < 2; half++) {
            int Arow = mbase + half * 8 + (lane >> 2);
            if (Arow < 127) {
                int na = Arow + 1;
                #pragma unroll
                for (int nt = 0; nt < 8; nt++) {
                    int e = nt * 8 + (lane & 3) * 2;
                    __nv_bfloat162 v;
                    v.x = __float2bfloat16_rn(d[nt][half * 2 + 0]);
                    v.y = __float2bfloat16_rn(d[nt][half * 2 + 1]);
                    *(__nv_bfloat162*)(arow + na * 64 + e) = v;
                }
            }
        }
    }
}

// =====================================================================
// K5: bf16 mma.sync GEMM: out[4096,256] = Abf @ Wfbf^T + bt*S + bf
//     CTA tile M=64 x N=128, 8 warps (2x4), warp tile 32x32,
//     K-chunks of 64, double-buffered cp.async, SW128 + ldmatrix.
// =====================================================================
__global__ __launch_bounds__(256) void k_final_mma(const float* __restrict__ bfv,
                                                   float* __restrict__ out) {
    __shared__ __align__(128) char sm8[49152];
    const uint32_t sb = smem_u32(sm8);
    const int tid = threadIdx.x, lane = tid & 31, w = tid >> 5;
    const int bm = blockIdx.x * 64, bn = blockIdx.y * 128;
    const int wm = (w & 1) * 32, wn = (w >> 1) * 32;
    const uint32_t Aoff[2] = {0u, 8192u};
    const uint32_t Boff[2] = {16384u, 32768u};

    float d[2][4][4] = {};

    auto loadChunk = [&](int t, int buf) {
        const __nv_bfloat16* Asrc = g_Abf + (size_t)bm * KTOT + (size_t)t * 64;
        #pragma unroll
        for (int i = 0; i < 2; i++) {
            int idx = tid + 256 * i;
            int row = idx >> 3, c = idx & 7;
            cp16(sb + Aoff[buf] + SWZ((uint32_t)(row * 128 + c * 16)),
                 Asrc + (size_t)row * KTOT + c * 8);
        }
        const __nv_bfloat16* Bsrc = g_Wfbf + (size_t)bn * KTOT + (size_t)t * 64;
        #pragma unroll
        for (int i = 0; i < 4; i++) {
            int idx = tid + 256 * i;
            int row = idx >> 3, c = idx & 7;
            cp16(sb + Boff[buf] + SWZ((uint32_t)(row * 128 + c * 16)),
                 Bsrc + (size_t)row * KTOT + c * 8);
        }
        CP_COMMIT();
    };

    loadChunk(0, 0);
    for (int t = 0; t < 128; t++) {
        const int buf = t & 1;
        if (t + 1 < 128) { loadChunk(t + 1, buf ^ 1); CP_WAIT(1); }
        else             { CP_WAIT(0); }
        __syncthreads();

        const uint32_t abase = sb + Aoff[buf];
        const uint32_t bbase = sb + Boff[buf];
        #pragma unroll
        for (int ks = 0; ks < 4; ks++) {
            uint32_t a[2][4], b[4][2];
            #pragma unroll
            for (int mt = 0; mt < 2; mt++) {
                uint32_t byte = (uint32_t)((wm + mt * 16 + (lane & 15)) * 128
                                           + (lane >> 4) * 16 + ks * 32);
                LDSM_X4(a[mt][0], a[mt][1], a[mt][2], a[mt][3], abase + SWZ(byte));
            }
            #pragma unroll
            for (int nr = 0; nr < 2; nr++) {
                uint32_t byte = (uint32_t)((wn + nr * 16 + (lane & 15)) * 128
                                           + (lane >> 4) * 16 + ks * 32);
                uint32_t r0, r1, r2, r3;
                LDSM_X4(r0, r1, r2, r3, bbase + SWZ(byte));
                b[nr * 2 + 0][0] = r0; b[nr * 2 + 0][1] = r2;
                b[nr * 2 + 1][0] = r1; b[nr * 2 + 1][1] = r3;
            }
            #pragma unroll
            for (int mt = 0; mt < 2; mt++)
                #pragma unroll
                for (int nt = 0; nt < 4; nt++)
                    MMA16816(d[mt][nt], a[mt], b[nt]);
        }
        __syncthreads();
    }

    const int nbase = bn + wn + (lane & 3) * 2;
    #pragma unroll
    for (int mt = 0; mt < 2; mt++) {
        #pragma unroll
        for (int half = 0; half < 2; half++) {
            int row = bm + wm + mt * 16 + half * 8 + (lane >> 2);
            float btv = g_bt[row];
            #pragma unroll
            for (int nt = 0; nt < 4; nt++) {
                int col = nbase + nt * 8;
                float v0 = d[mt][nt][half * 2 + 0] + btv * g_S[col]     + bfv[col];
                float v1 = d[mt][nt][half * 2 + 1] + btv * g_S[col + 1] + bfv[col + 1];
                *(float2*)&out[(size_t)row * RNN + col] = make_float2(v0, v1);
            }
        }
    }
}

// =====================================================================
// launch
// =====================================================================
extern "C" void kernel_launch(void* const* d_in, const int* in_sizes, int n_in,
                              void* d_out, int out_size) {
    const float* obs  = (const float*)d_in[0];
    const float* Wq1  = (const float*)d_in[1];
    const float* bq1  = (const float*)d_in[2];
    const float* Wq2  = (const float*)d_in[3];
    const float* Wkm1 = (const float*)d_in[4];
    const float* bkm1 = (const float*)d_in[5];
    const float* Wkm2 = (const float*)d_in[6];
    const float* Wke  = (const float*)d_in[7];
    const float* Wka  = (const float*)d_in[8];
    const float* Wvm1 = (const float*)d_in[9];
    const float* bvm1 = (const float*)d_in[10];
    const float* Wvm2 = (const float*)d_in[11];
    const float* Wve  = (const float*)d_in[12];
    const float* Wva  = (const float*)d_in[13];
    const float* Wb1  = (const float*)d_in[14];
    const float* bb1  = (const float*)d_in[15];
    const float* Wb2  = (const float*)d_in[16];
    const float* bb2  = (const float*)d_in[17];
    const float* Wh1  = (const float*)d_in[18];
    const float* bh1  = (const float*)d_in[19];
    const float* Wh2  = (const float*)d_in[20];
    const float* bh2  = (const float*)d_in[21];
    const float* Wf   = (const float*)d_in[22];
    const float* bf   = (const float*)d_in[23];
    float* out = (float*)d_out;

    k_prep<<<257, 256>>>(Wf, Wve, Wva);
    k_front<<<dim3(64, 3), 256>>>(obs, Wb1, bb1, Wh1, bh1);
    k_post_front<<<512, 256>>>(Wb2, bb2, Wh2, bh2);
    k_h1<<<dim3(64, 24), 256>>>(obs, Wq1, bq1, Wkm1, bkm1, Wvm1, bvm1);
    k_qkv<<<dim3(64, 12), 256>>>(Wq2, Wkm2, Wvm2);
    k_fold<<<4096, 128>>>(Wke, Wka);
    k_attn<<<4096, 256>>>(obs);
    k_final_mma<<<dim3(64, 2), 256>>>(bf, out);
}

// round 6
// speedup vs baseline: 7.6152x; 1.7434x over previous
#include <cuda_runtime.h>
#include <cuda_bf16.h>
#include <cstdint>
#include <cstddef>

// ---------------- problem dims ----------------
#define BS 4096
#define IN 2056
#define MF 24
#define H 4
#define HE 128
#define E 64
#define NA 128
#define RNN 256
#define KTOT 8192         // E*NA
#define KF 2080           // front K in uint32 (bf16x2 hi/lo pairs), 65 chunks of 32

// ---------------- scratch (device globals; no allocs allowed) ----------------
__device__ float g_hid[BS * 192];
__device__ float g_bt[BS];
__device__ float g_wh[BS * H];
__device__ float g_q[BS * H * E];
__device__ float g_km[BS * H * E];
__device__ float g_vm[BS * H * E];
__device__ float g_te[BS * H * 16];
__device__ float g_ta[BS * H * 16];
__device__ float g_l0[BS * H];
__device__ float g_S[RNN];
// A for final GEMM, layout [b][na*64+e]  (PERMUTED k-index)
__device__ __align__(16) __nv_bfloat16 g_Abf[(size_t)BS * KTOT];
// Wf in bf16, same permuted layout
__device__ __align__(16) __nv_bfloat16 g_Wfbf[(size_t)RNN * KTOT];
// flattened value weights: [sel][e][h*16+d]
__device__ __align__(16) __nv_bfloat16 g_Wvbf[2 * 64 * 64];
// obs split hi/lo interleaved: [4096][KF] uint32 (pad cols zero-init)
__device__ __align__(16) uint32_t g_obsbf2[(size_t)BS * KF];
// front weights [pass 0=hi,1=lo][192][KF] uint32
__device__ __align__(16) uint32_t g_WB[(size_t)2 * 192 * KF];

// ---------------- PTX helpers ----------------
__device__ __forceinline__ uint32_t smem_u32(const void* p) {
    uint32_t a;
    asm("{ .reg .u64 t; cvta.to.shared.u64 t, %1; cvt.u32.u64 %0, t; }" : "=r"(a) : "l"(p));
    return a;
}
__device__ __forceinline__ void cp16(uint32_t dst, const void* src) {
    asm volatile("cp.async.cg.shared.global [%0], [%1], 16;" :: "r"(dst), "l"(src) : "memory");
}
#define CP_COMMIT() asm volatile("cp.async.commit_group;" ::: "memory")
#define CP_WAIT(n)  asm volatile("cp.async.wait_group %0;" :: "n"(n) : "memory")

#define LDSM_X4(r0, r1, r2, r3, addr) \
    asm volatile("ldmatrix.sync.aligned.m8n8.x4.shared.b16 {%0,%1,%2,%3}, [%4];" \
                 : "=r"(r0), "=r"(r1), "=r"(r2), "=r"(r3) : "r"(addr))

#define MMA16816(d, a, b) \
    asm volatile("mma.sync.aligned.m16n8k16.row.col.f32.bf16.bf16.f32 " \
                 "{%0,%1,%2,%3}, {%4,%5,%6,%7}, {%8,%9}, {%0,%1,%2,%3};" \
                 : "+f"((d)[0]), "+f"((d)[1]), "+f"((d)[2]), "+f"((d)[3]) \
                 : "r"((a)[0]), "r"((a)[1]), "r"((a)[2]), "r"((a)[3]), \
                   "r"((b)[0]), "r"((b)[1]))

#define SWZ(x) ((x) ^ (((x) >> 3) & 0x70))

// =====================================================================
// K0: prep — blocks 0..255: Wf row -> permuted bf16 + S[r]
//           block 256: flatten Wve/Wva
//           blocks 257..448: front weights hi/lo
// =====================================================================
__global__ __launch_bounds__(256) void k_prep(const float* __restrict__ Wf,
                                              const float* __restrict__ Wve,
                                              const float* __restrict__ Wva,
                                              const float* __restrict__ Wb1,
                                              const float* __restrict__ Wh1) {
    int r = blockIdx.x;
    int tid = threadIdx.x;
    if (r < 256) {
        __shared__ float row[8256];
        __shared__ float red[8];
        float s = 0.f;
        for (int i = tid; i < 8192; i += 256) {
            float v = Wf[(size_t)r * 8192 + i];
            row[i + (i >> 7)] = v;
            s += v;
        }
        #pragma unroll
        for (int o = 16; o; o >>= 1) s += __shfl_xor_sync(0xffffffffu, s, o);
        if ((tid & 31) == 0) red[tid >> 5] = s;
        __syncthreads();
        if (tid == 0) {
            float t = 0.f;
            #pragma unroll
            for (int j = 0; j < 8; j++) t += red[j];
            g_S[r] = t;
        }
        for (int i = tid; i < 8192; i += 256) {
            int na = i >> 6, e = i & 63;
            int src = e * 128 + na;
            g_Wfbf[(size_t)r * 8192 + i] = __float2bfloat16_rn(row[src + (src >> 7)]);
        }
    } else if (r == 256) {
        for (int i = tid; i < 8192; i += 256) {
            int sel = i >> 12, j = i & 4095;
            int e = j >> 6, hd = j & 63, h = hd >> 4, d = hd & 15;
            const float* W = sel ? Wva : Wve;
            g_Wvbf[i] = __float2bfloat16_rn(W[h * 1024 + e * 16 + d]);
        }
    } else {
        int n = r - 257;   // 0..191
        const float* W = (n < 64) ? (Wb1 + (size_t)n * IN) : (Wh1 + (size_t)(n - 64) * IN);
        uint32_t* d0 = g_WB + (size_t)n * KF;
        uint32_t* d1 = g_WB + (size_t)192 * KF + (size_t)n * KF;
        for (int k = tid; k < IN; k += 256) {
            float x = W[k];
            __nv_bfloat16 hi = __float2bfloat16_rn(x);
            __nv_bfloat16 lo = __float2bfloat16_rn(x - __bfloat162float(hi));
            __nv_bfloat162 p0; p0.x = hi; p0.y = hi;
            __nv_bfloat162 p1; p1.x = lo; p1.y = lo;
            d0[k] = *(uint32_t*)&p0;
            d1[k] = *(uint32_t*)&p1;
        }
    }
}

// =====================================================================
// K0b: convert obs -> interleaved hi/lo bf16 pairs
// =====================================================================
__global__ __launch_bounds__(256) void k_cvt(const float* __restrict__ obs) {
    int row = blockIdx.x;
    const float* src = obs + (size_t)row * IN;
    uint32_t* dst = g_obsbf2 + (size_t)row * KF;
    for (int k = threadIdx.x; k < IN; k += 256) {
        float x = src[k];
        __nv_bfloat16 hi = __float2bfloat16_rn(x);
        __nv_bfloat16 lo = __float2bfloat16_rn(x - __bfloat162float(hi));
        __nv_bfloat162 p; p.x = hi; p.y = lo;
        dst[k] = *(uint32_t*)&p;
    }
}

// =====================================================================
// K1: front GEMM (tensor, split-bf16 exact):
//     g_hid[4096,192] = relu(obs @ [Wb1;Wh1]^T + bias)
//     CTA M=64 N=64; per K-chunk both B passes accumulate into same d.
// =====================================================================
__global__ __launch_bounds__(256) void k_front_tc(const float* __restrict__ bb1,
                                                  const float* __restrict__ bh1) {
    __shared__ __align__(128) char sm8[49152];
    const uint32_t sb = smem_u32(sm8);
    const int tid = threadIdx.x, lane = tid & 31, w = tid >> 5;
    const int bm = blockIdx.x * 64, bn = blockIdx.y * 64;
    const int wm = (w & 3) * 16, wn = (w >> 2) * 32;
    // A[2]@0/8192 ; B0[2]@16384/24576 ; B1[2]@32768/40960
    float d[4][4] = {};

    auto loadChunk = [&](int t, int buf) {
        #pragma unroll
        for (int i = 0; i < 2; i++) {
            int idx = tid + 256 * i;
            int row = idx >> 3, c16 = idx & 7;
            cp16(sb + buf * 8192 + SWZ((uint32_t)(row * 128 + c16 * 16)),
                 g_obsbf2 + (size_t)(bm + row) * KF + t * 32 + c16 * 4);
        }
        #pragma unroll
        for (int i = 0; i < 2; i++) {
            int idx = tid + 256 * i;
            int row = idx >> 3, c16 = idx & 7;
            const uint32_t* s0 = g_WB + (size_t)(bn + row) * KF + t * 32 + c16 * 4;
            uint32_t off = SWZ((uint32_t)(row * 128 + c16 * 16));
            cp16(sb + 16384 + buf * 8192 + off, s0);
            cp16(sb + 32768 + buf * 8192 + off, s0 + (size_t)192 * KF);
        }
        CP_COMMIT();
    };

    loadChunk(0, 0);
    for (int t = 0; t < 65; t++) {
        const int buf = t & 1;
        if (t < 64) { loadChunk(t + 1, buf ^ 1); CP_WAIT(1); }
        else        { CP_WAIT(0); }
        __syncthreads();
        const uint32_t ab = sb + buf * 8192;
        const uint32_t b0b = sb + 16384 + buf * 8192;
        const uint32_t b1b = sb + 32768 + buf * 8192;
        #pragma unroll
        for (int ks = 0; ks < 4; ks++) {
            uint32_t a[4];
            uint32_t byte = (uint32_t)((wm + (lane & 15)) * 128 + (lane >> 4) * 16 + ks * 32);
            LDSM_X4(a[0], a[1], a[2], a[3], ab + SWZ(byte));
            uint32_t b0[4][2], b1[4][2];
            #pragma unroll
            for (int nr = 0; nr < 2; nr++) {
                uint32_t by2 = (uint32_t)((wn + nr * 16 + (lane & 15)) * 128
                                          + (lane >> 4) * 16 + ks * 32);
                uint32_t r0, r1, r2, r3;
                LDSM_X4(r0, r1, r2, r3, b0b + SWZ(by2));
                b0[nr * 2][0] = r0; b0[nr * 2][1] = r2;
                b0[nr * 2 + 1][0] = r1; b0[nr * 2 + 1][1] = r3;
                LDSM_X4(r0, r1, r2, r3, b1b + SWZ(by2));
                b1[nr * 2][0] = r0; b1[nr * 2][1] = r2;
                b1[nr * 2 + 1][0] = r1; b1[nr * 2 + 1][1] = r3;
            }
            #pragma unroll
            for (int nt = 0; nt < 4; nt++) {
                MMA16816(d[nt], a, b0[nt]);
                MMA16816(d[nt], a, b1[nt]);
            }
        }
        __syncthreads();
    }

    #pragma unroll
    for (int half = 0; half < 2; half++) {
        int row = bm + wm + half * 8 + (lane >> 2);
        #pragma unroll
        for (int nt = 0; nt < 4; nt++) {
            int n = bn + wn + nt * 8 + (lane & 3) * 2;
            float bias0 = (n < 64) ? bb1[n] : bh1[n - 64];
            float bias1 = (n + 1 < 64) ? bb1[n + 1] : bh1[n + 1 - 64];
            float v0 = fmaxf(d[nt][half * 2 + 0] + bias0, 0.f);
            float v1 = fmaxf(d[nt][half * 2 + 1] + bias1, 0.f);
            *(float2*)&g_hid[row * 192 + n] = make_float2(v0, v1);
        }
    }
}

// =====================================================================
// K2: b_term + w_head from hid
// =====================================================================
__global__ __launch_bounds__(256) void k_post_front(const float* __restrict__ Wb2,
                                                    const float* __restrict__ bb2,
                                                    const float* __restrict__ Wh2,
                                                    const float* __restrict__ bh2) {
    int warp = threadIdx.x >> 5, lane = threadIdx.x & 31;
    int b = blockIdx.x * 8 + warp;
    const float* hrow = g_hid + b * 192;
    float s = hrow[lane] * Wb2[lane] + hrow[32 + lane] * Wb2[32 + lane];
    #pragma unroll
    for (int o = 16; o; o >>= 1) s += __shfl_xor_sync(0xffffffffu, s, o);
    if (lane == 0) g_bt[b] = s + bb2[0];
    #pragma unroll
    for (int h = 0; h < H; h++) {
        float t = 0.f;
        #pragma unroll
        for (int j = lane; j < HE; j += 32) t += hrow[64 + j] * Wh2[h * HE + j];
        #pragma unroll
        for (int o = 16; o; o >>= 1) t += __shfl_xor_sync(0xffffffffu, t, o);
        if (lane == 0) g_wh[b * H + h] = fabsf(t + bh2[h]);
    }
}

// =====================================================================
// K3: fused m-MLPs: per (128-batch block, mlp, head):
//     stage1 (FFMA): h1 = relu(m @ W1_h^T + b1) -> smem bf16
//     stage2 (mma):  out = h1 @ W2_h^T -> g_q/g_km/g_vm fp32
// smem layout (bytes): msm f32[128*25]@0, w1 f32[128*25]@12800,
//   b1 f32[128]@25600, h1 bf16 2x[128][64]@26112, w2 bf16 2x[64][64]@58880
// =====================================================================
__global__ __launch_bounds__(256) void k_mlp(const float* __restrict__ obs,
                                             const float* __restrict__ Wq1, const float* __restrict__ bq1,
                                             const float* __restrict__ Wq2,
                                             const float* __restrict__ Wkm1, const float* __restrict__ bkm1,
                                             const float* __restrict__ Wkm2,
                                             const float* __restrict__ Wvm1, const float* __restrict__ bvm1,
                                             const float* __restrict__ Wvm2) {
    extern __shared__ __align__(128) char smp[];
    float* msm = (float*)smp;
    float* w1s = (float*)(smp + 12800);
    float* b1s = (float*)(smp + 25600);
    char* h1B = smp + 26112;
    char* w2B = smp + 58880;

    const int tid = threadIdx.x, lane = tid & 31;
    const int bm = blockIdx.x * 128;
    const int mlp = blockIdx.y >> 2, h = blockIdx.y & 3;
    const float* W1 = ((mlp == 0) ? Wq1 : (mlp == 1) ? Wkm1 : Wvm1) + h * HE * MF;
    const float* B1 = ((mlp == 0) ? bq1 : (mlp == 1) ? bkm1 : bvm1) + h * HE;
    const float* W2 = ((mlp == 0) ? Wq2 : (mlp == 1) ? Wkm2 : Wvm2) + h * E * HE;
    float* outp = (mlp == 0) ? g_q : (mlp == 1) ? g_km : g_vm;

    // loads
    for (int i = tid; i < 128 * 24; i += 256) {
        int r = i / 24, f = i - r * 24;
        int col = (f < 4) ? f : (2032 + f);
        msm[r * 25 + f] = obs[(size_t)(bm + r) * IN + col];
    }
    for (int i = tid; i < 128 * 24; i += 256) {
        int g = i / 24, f = i - g * 24;
        w1s[g * 25 + f] = W1[g * 24 + f];
    }
    if (tid < 128) b1s[tid] = B1[tid];
    // w2 -> bf16 smem panels (kk = g>=64), vectorized 8 floats -> uint4
    for (int i = tid; i < 1024; i += 256) {
        int e = i >> 4, g8 = (i & 15) * 8;
        int kk = g8 >> 6, wi = g8 & 63;
        const float* src = W2 + e * HE + g8;
        float4 v0 = *(const float4*)src;
        float4 v1 = *(const float4*)(src + 4);
        __nv_bfloat162 p[4];
        p[0] = __floats2bfloat162_rn(v0.x, v0.y);
        p[1] = __floats2bfloat162_rn(v0.z, v0.w);
        p[2] = __floats2bfloat162_rn(v1.x, v1.y);
        p[3] = __floats2bfloat162_rn(v1.z, v1.w);
        *(uint4*)(w2B + kk * 8192 + SWZ((uint32_t)(e * 128 + wi * 2))) = *(uint4*)p;
    }
    __syncthreads();

    // stage1: each thread: one row, one 64-col half
    {
        int r = tid & 127, chalf = tid >> 7;
        float mreg[24];
        #pragma unroll
        for (int f = 0; f < 24; f++) mreg[f] = msm[r * 25 + f];
        char* pan = h1B + chalf * 16384;
        #pragma unroll 4
        for (int c = 0; c < 64; c += 2) {
            int cc = chalf * 64 + c;
            float a0 = b1s[cc], a1 = b1s[cc + 1];
            const float* w0 = w1s + cc * 25;
            #pragma unroll
            for (int f = 0; f < 24; f++) {
                a0 += mreg[f] * w0[f];
                a1 += mreg[f] * w0[25 + f];
            }
            __nv_bfloat162 p = __floats2bfloat162_rn(fmaxf(a0, 0.f), fmaxf(a1, 0.f));
            *(__nv_bfloat162*)(pan + SWZ((uint32_t)(r * 128 + c * 2))) = p;
        }
    }
    __syncthreads();

    // stage2: M=128 N=64 K=128 mma; warps: 2 m-groups x 4 n-groups
    {
        int w = tid >> 5;
        int wm = (w & 1) * 64, wn = (w >> 1) * 16;
        uint32_t h1b = smem_u32(h1B);
        uint32_t w2b = smem_u32(w2B);
        float d[4][2][4] = {};
        #pragma unroll
        for (int kk = 0; kk < 2; kk++) {
            uint32_t ab = h1b + kk * 16384;
            uint32_t bb = w2b + kk * 8192;
            #pragma unroll
            for (int ks = 0; ks < 4; ks++) {
                uint32_t bfr[2][2];
                {
                    uint32_t by = (uint32_t)((wn + (lane & 15)) * 128 + (lane >> 4) * 16 + ks * 32);
                    uint32_t r0, r1, r2, r3;
                    LDSM_X4(r0, r1, r2, r3, bb + SWZ(by));
                    bfr[0][0] = r0; bfr[0][1] = r2;
                    bfr[1][0] = r1; bfr[1][1] = r3;
                }
                #pragma unroll
                for (int mt = 0; mt < 4; mt++) {
                    uint32_t a[4];
                    uint32_t by = (uint32_t)((wm + mt * 16 + (lane & 15)) * 128
                                             + (lane >> 4) * 16 + ks * 32);
                    LDSM_X4(a[0], a[1], a[2], a[3], ab + SWZ(by));
                    MMA16816(d[mt][0], a, bfr[0]);
                    MMA16816(d[mt][1], a, bfr[1]);
                }
            }
        }
        #pragma unroll
        for (int mt = 0; mt < 4; mt++)
            #pragma unroll
            for (int half = 0; half < 2; half++) {
                int row = bm + wm + mt * 16 + half * 8 + (lane >> 2);
                #pragma unroll
                for (int nt = 0; nt < 2; nt++) {
                    int e = wn + nt * 8 + (lane & 3) * 2;
                    *(float2*)&outp[(size_t)row * 256 + h * 64 + e] =
                        make_float2(d[mt][nt][half * 2], d[mt][nt][half * 2 + 1]);
                }
            }
    }
}

// =====================================================================
// K3c: fold keys into query: te/ta = (q^T Wk)/8, l0 = (q.km)/8
// =====================================================================
__global__ __launch_bounds__(128) void k_fold(const float* __restrict__ Wke,
                                              const float* __restrict__ Wka) {
    int b = blockIdx.x;
    __shared__ float qs[256], kms[256];
    int tid = threadIdx.x;
    qs[tid] = g_q[b * 256 + tid];
    qs[tid + 128] = g_q[b * 256 + 128 + tid];
    kms[tid] = g_km[b * 256 + tid];
    kms[tid + 128] = g_km[b * 256 + 128 + tid];
    __syncthreads();
    {
        int h = (tid & 63) >> 4, d = tid & 15;
        const float* Wk = (tid < 64) ? Wke : Wka;
        float s = 0.f;
        #pragma unroll
        for (int e = 0; e < 64; e++) s += qs[h * 64 + e] * Wk[h * 1024 + e * 16 + d];
        s *= 0.125f;
        if (tid < 64) g_te[b * 64 + h * 16 + d] = s;
        else          g_ta[b * 64 + h * 16 + d] = s;
    }
    int w = tid >> 5, lane = tid & 31;
    float s = qs[w * 64 + lane] * kms[w * 64 + lane] +
              qs[w * 64 + 32 + lane] * kms[w * 64 + 32 + lane];
    #pragma unroll
    for (int o = 16; o; o >>= 1) s += __shfl_xor_sync(0xffffffffu, s, o);
    if (lane == 0) g_l0[b * 4 + w] = s * 0.125f;
}

// =====================================================================
// K4: per-batch attention + tensor-core mix -> g_Abf
// =====================================================================
__global__ __launch_bounds__(256) void k_attn(const float* __restrict__ obs) {
    __shared__ float ent[2032];
    __shared__ float lg[512];
    __shared__ float u[512];
    __shared__ float vms[256];
    __shared__ float tv[128];
    __shared__ float whl[8];
    __shared__ __align__(128) __nv_bfloat16 Zs[128 * 64];
    __shared__ __align__(128) __nv_bfloat16 Wvs[128 * 64];

    int b = blockIdx.x, tid = threadIdx.x;
    char* ZsB = (char*)Zs;
    char* WvsB = (char*)Wvs;

    const float* orow = obs + (size_t)b * IN;
    for (int i = tid; i < 2032; i += 256) ent[i] = orow[4 + i];
    {
        const uint4* wsrc = (const uint4*)g_Wvbf;
        #pragma unroll
        for (int i = tid; i < 1024; i += 256) {
            int row = i >> 3, c = i & 7;
            *(uint4*)(WvsB + SWZ((uint32_t)(row * 128 + c * 16))) = wsrc[i];
        }
    }
    vms[tid & 255] = g_vm[b * 256 + (tid & 255)];
    if (tid < 64) { tv[tid] = g_te[b * 64 + tid]; tv[64 + tid] = g_ta[b * 64 + tid]; }
    if (tid < 8) whl[tid] = (tid < 4) ? g_wh[b * 4 + tid] : g_l0[b * 4 + (tid - 4)];
    __syncthreads();

    for (int i = tid; i < 508; i += 256) {
        int h = i / 127, n = i - h * 127;
        const float* tp = tv + ((n < 64) ? 0 : 64) + h * 16;
        const float* ep = ent + n * 16;
        float s = 0.f;
        #pragma unroll
        for (int d = 0; d < 16; d++) s += ep[d] * tp[d];
        lg[h * 128 + 1 + n] = s;
    }
    if (tid < 4) lg[tid * 128] = whl[4 + tid];
    __syncthreads();

    if (tid < 128) {
        int h = tid >> 5, lane = tid & 31;
        float v0[4], m0 = -3.4e38f;
        #pragma unroll
        for (int j = 0; j < 4; j++) { v0[j] = lg[h * 128 + lane + 32 * j]; m0 = fmaxf(m0, v0[j]); }
        #pragma unroll
        for (int o = 16; o; o >>= 1) m0 = fmaxf(m0, __shfl_xor_sync(0xffffffffu, m0, o));
        float ss = 0.f;
        #pragma unroll
        for (int j = 0; j < 4; j++) { v0[j] = expf(v0[j] - m0); ss += v0[j]; }
        #pragma unroll
        for (int o = 16; o; o >>= 1) ss += __shfl_xor_sync(0xffffffffu, ss, o);
        float sc = whl[h] / ss;
        #pragma unroll
        for (int j = 0; j < 4; j++) u[h * 128 + lane + 32 * j] = v0[j] * sc;
    }
    __syncthreads();

    #pragma unroll
    for (int i = tid; i < 8192; i += 256) {
        int n = i >> 6, hd = i & 63;
        float val = 0.f;
        if (n < 127) {
            int h = hd >> 4, d = hd & 15;
            val = u[h * 128 + n + 1] * ent[n * 16 + d];
        }
        *(__nv_bfloat16*)(ZsB + SWZ((uint32_t)(n * 128 + hd * 2))) = __float2bfloat16_rn(val);
    }
    __nv_bfloat16* arow = g_Abf + (size_t)b * KTOT;
    if (tid < 64) {
        float s = 0.f;
        #pragma unroll
        for (int h = 0; h < 4; h++) s += u[h * 128] * vms[h * 64 + tid];
        arow[tid] = __float2bfloat16_rn(s);
    }
    __syncthreads();

    {
        int w = tid >> 5, lane = tid & 31;
        int sel = w >> 2;
        int mbase = w * 16;
        uint32_t zb = smem_u32(Zs);
        uint32_t wb = smem_u32(Wvs) + (uint32_t)sel * 8192u;
        float d[8][4] = {};
        #pragma unroll
        for (int ks = 0; ks < 4; ks++) {
            uint32_t a[4];
            uint32_t byte = (uint32_t)((mbase + (lane & 15)) * 128 + (lane >> 4) * 16 + ks * 32);
            LDSM_X4(a[0], a[1], a[2], a[3], zb + SWZ(byte));
            uint32_t bfr[8][2];
            #pragma unroll
            for (int nr = 0; nr < 4; nr++) {
                uint32_t byte2 = (uint32_t)((nr * 16 + (lane & 15)) * 128 + (lane >> 4) * 16 + ks * 32);
                uint32_t r0, r1, r2, r3;
                LDSM_X4(r0, r1, r2, r3, wb + SWZ(byte2));
                bfr[nr * 2 + 0][0] = r0; bfr[nr * 2 + 0][1] = r2;
                bfr[nr * 2 + 1][0] = r1; bfr[nr * 2 + 1][1] = r3;
            }
            #pragma unroll
            for (int nt = 0; nt < 8; nt++) MMA16816(d[nt], a, bfr[nt]);
        }
        #pragma unroll
        for (int half = 0; half < 2; half++) {
            int Arow = mbase + half * 8 + (lane >> 2);
            if (Arow < 127) {
                int na = Arow + 1;
                #pragma unroll
                for (int nt = 0; nt < 8; nt++) {
                    int e = nt * 8 + (lane & 3) * 2;
                    __nv_bfloat162 v;
                    v.x = __float2bfloat16_rn(d[nt][half * 2 + 0]);
                    v.y = __float2bfloat16_rn(d[nt][half * 2 + 1]);
                    *(__nv_bfloat162*)(arow + na * 64 + e) = v;
                }
            }
        }
    }
}

// =====================================================================
// K5: bf16 mma GEMM: out[4096,256] = Abf @ Wfbf^T + bt*S + bf
// =====================================================================
__global__ __launch_bounds__(256) void k_final_mma(const float* __restrict__ bfv,
                                                   float* __restrict__ out) {
    __shared__ __align__(128) char sm8[49152];
    const uint32_t sb = smem_u32(sm8);
    const int tid = threadIdx.x, lane = tid & 31, w = tid >> 5;
    const int bm = blockIdx.x * 64, bn = blockIdx.y * 128;
    const int wm = (w & 1) * 32, wn = (w >> 1) * 32;
    const uint32_t Aoff[2] = {0u, 8192u};
    const uint32_t Boff[2] = {16384u, 32768u};

    float d[2][4][4] = {};

    auto loadChunk = [&](int t, int buf) {
        const __nv_bfloat16* Asrc = g_Abf + (size_t)bm * KTOT + (size_t)t * 64;
        #pragma unroll
        for (int i = 0; i < 2; i++) {
            int idx = tid + 256 * i;
            int row = idx >> 3, c = idx & 7;
            cp16(sb + Aoff[buf] + SWZ((uint32_t)(row * 128 + c * 16)),
                 Asrc + (size_t)row * KTOT + c * 8);
        }
        const __nv_bfloat16* Bsrc = g_Wfbf + (size_t)bn * KTOT + (size_t)t * 64;
        #pragma unroll
        for (int i = 0; i < 4; i++) {
            int idx = tid + 256 * i;
            int row = idx >> 3, c = idx & 7;
            cp16(sb + Boff[buf] + SWZ((uint32_t)(row * 128 + c * 16)),
                 Bsrc + (size_t)row * KTOT + c * 8);
        }
        CP_COMMIT();
    };

    loadChunk(0, 0);
    for (int t = 0; t < 128; t++) {
        const int buf = t & 1;
        if (t + 1 < 128) { loadChunk(t + 1, buf ^ 1); CP_WAIT(1); }
        else             { CP_WAIT(0); }
        __syncthreads();

        const uint32_t abase = sb + Aoff[buf];
        const uint32_t bbase = sb + Boff[buf];
        #pragma unroll
        for (int ks = 0; ks < 4; ks++) {
            uint32_t a[2][4], b[4][2];
            #pragma unroll
            for (int mt = 0; mt < 2; mt++) {
                uint32_t byte = (uint32_t)((wm + mt * 16 + (lane & 15)) * 128
                                           + (lane >> 4) * 16 + ks * 32);
                LDSM_X4(a[mt][0], a[mt][1], a[mt][2], a[mt][3], abase + SWZ(byte));
            }
            #pragma unroll
            for (int nr = 0; nr < 2; nr++) {
                uint32_t byte = (uint32_t)((wn + nr * 16 + (lane & 15)) * 128
                                           + (lane >> 4) * 16 + ks * 32);
                uint32_t r0, r1, r2, r3;
                LDSM_X4(r0, r1, r2, r3, bbase + SWZ(byte));
                b[nr * 2 + 0][0] = r0; b[nr * 2 + 0][1] = r2;
                b[nr * 2 + 1][0] = r1; b[nr * 2 + 1][1] = r3;
            }
            #pragma unroll
            for (int mt = 0; mt < 2; mt++)
                #pragma unroll
                for (int nt = 0; nt < 4; nt++)
                    MMA16816(d[mt][nt], a[mt], b[nt]);
        }
        __syncthreads();
    }

    const int nbase = bn + wn + (lane & 3) * 2;
    #pragma unroll
    for (int mt = 0; mt < 2; mt++) {
        #pragma unroll
        for (int half = 0; half < 2; half++) {
            int row = bm + wm + mt * 16 + half * 8 + (lane >> 2);
            float btv = g_bt[row];
            #pragma unroll
            for (int nt = 0; nt < 4; nt++) {
                int col = nbase + nt * 8;
                float v0 = d[mt][nt][half * 2 + 0] + btv * g_S[col]     + bfv[col];
                float v1 = d[mt][nt][half * 2 + 1] + btv * g_S[col + 1] + bfv[col + 1];
                *(float2*)&out[(size_t)row * RNN + col] = make_float2(v0, v1);
            }
        }
    }
}

// =====================================================================
// launch
// =====================================================================
extern "C" void kernel_launch(void* const* d_in, const int* in_sizes, int n_in,
                              void* d_out, int out_size) {
    const float* obs  = (const float*)d_in[0];
    const float* Wq1  = (const float*)d_in[1];
    const float* bq1  = (const float*)d_in[2];
    const float* Wq2  = (const float*)d_in[3];
    const float* Wkm1 = (const float*)d_in[4];
    const float* bkm1 = (const float*)d_in[5];
    const float* Wkm2 = (const float*)d_in[6];
    const float* Wke  = (const float*)d_in[7];
    const float* Wka  = (const float*)d_in[8];
    const float* Wvm1 = (const float*)d_in[9];
    const float* bvm1 = (const float*)d_in[10];
    const float* Wvm2 = (const float*)d_in[11];
    const float* Wve  = (const float*)d_in[12];
    const float* Wva  = (const float*)d_in[13];
    const float* Wb1  = (const float*)d_in[14];
    const float* bb1  = (const float*)d_in[15];
    const float* Wb2  = (const float*)d_in[16];
    const float* bb2  = (const float*)d_in[17];
    const float* Wh1  = (const float*)d_in[18];
    const float* bh1  = (const float*)d_in[19];
    const float* Wh2  = (const float*)d_in[20];
    const float* bh2  = (const float*)d_in[21];
    const float* Wf   = (const float*)d_in[22];
    const float* bf   = (const float*)d_in[23];
    float* out = (float*)d_out;

    const int mlp_smem = 75264;
    cudaFuncSetAttribute(k_mlp, cudaFuncAttributeMaxDynamicSharedMemorySize, mlp_smem);

    k_prep<<<449, 256>>>(Wf, Wve, Wva, Wb1, Wh1);
    k_cvt<<<4096, 256>>>(obs);
    k_front_tc<<<dim3(64, 3), 256>>>(bb1, bh1);
    k_post_front<<<512, 256>>>(Wb2, bb2, Wh2, bh2);
    k_mlp<<<dim3(32, 12), 256, mlp_smem>>>(obs, Wq1, bq1, Wq2, Wkm1, bkm1, Wkm2,
                                           Wvm1, bvm1, Wvm2);
    k_fold<<<4096, 128>>>(Wke, Wka);
    k_attn<<<4096, 256>>>(obs);
    k_final_mma<<<dim3(64, 2), 256>>>(bf, out);
}

// round 7
// speedup vs baseline: 7.8383x; 1.0293x over previous
#include <cuda_runtime.h>
#include <cuda_bf16.h>
#include <cstdint>
#include <cstddef>

// ---------------- problem dims ----------------
#define BS 4096
#define IN 2056
#define MF 24
#define H 4
#define HE 128
#define E 64
#define NA 128
#define RNN 256
#define KTOT 8192         // E*NA
#define KF 2080           // front K in uint32 (bf16x2 pairs), 65 chunks of 32

// ---------------- scratch (device globals; no allocs allowed) ----------------
__device__ float g_hid[BS * 192];
__device__ float g_bt[BS];
__device__ float g_q[BS * H * E];
__device__ float g_km[BS * H * E];
__device__ float g_vm[BS * H * E];
__device__ float g_S[RNN];
// A for final GEMM, layout [b][na*64+e]  (PERMUTED k-index)
__device__ __align__(16) __nv_bfloat16 g_Abf[(size_t)BS * KTOT];
// Wf in bf16, same permuted layout
__device__ __align__(16) __nv_bfloat16 g_Wfbf[(size_t)RNN * KTOT];
// flattened value weights: [sel][e][h*16+d]
__device__ __align__(16) __nv_bfloat16 g_Wvbf[2 * 64 * 64];
// front weights [pass 0=hi,1=lo][192][KF] uint32 (pad cols stay zero)
__device__ __align__(16) uint32_t g_WB[(size_t)2 * 192 * KF];

// ---------------- PTX helpers ----------------
__device__ __forceinline__ uint32_t smem_u32(const void* p) {
    uint32_t a;
    asm("{ .reg .u64 t; cvta.to.shared.u64 t, %1; cvt.u32.u64 %0, t; }" : "=r"(a) : "l"(p));
    return a;
}
__device__ __forceinline__ void cp16(uint32_t dst, const void* src) {
    asm volatile("cp.async.cg.shared.global [%0], [%1], 16;" :: "r"(dst), "l"(src) : "memory");
}
#define CP_COMMIT() asm volatile("cp.async.commit_group;" ::: "memory")
#define CP_WAIT(n)  asm volatile("cp.async.wait_group %0;" :: "n"(n) : "memory")

#define LDSM_X4(r0, r1, r2, r3, addr) \
    asm volatile("ldmatrix.sync.aligned.m8n8.x4.shared.b16 {%0,%1,%2,%3}, [%4];" \
                 : "=r"(r0), "=r"(r1), "=r"(r2), "=r"(r3) : "r"(addr))

#define MMA16816(d, a, b) \
    asm volatile("mma.sync.aligned.m16n8k16.row.col.f32.bf16.bf16.f32 " \
                 "{%0,%1,%2,%3}, {%4,%5,%6,%7}, {%8,%9}, {%0,%1,%2,%3};" \
                 : "+f"((d)[0]), "+f"((d)[1]), "+f"((d)[2]), "+f"((d)[3]) \
                 : "r"((a)[0]), "r"((a)[1]), "r"((a)[2]), "r"((a)[3]), \
                   "r"((b)[0]), "r"((b)[1]))

#define SWZ(x) ((x) ^ (((x) >> 3) & 0x70))

// =====================================================================
// K0: prep — blocks 0..255: Wf row -> permuted bf16 + S[r]
//           block 256: flatten Wve/Wva
//           blocks 257..448: front weights hi/lo
// =====================================================================
__global__ __launch_bounds__(256) void k_prep(const float* __restrict__ Wf,
                                              const float* __restrict__ Wve,
                                              const float* __restrict__ Wva,
                                              const float* __restrict__ Wb1,
                                              const float* __restrict__ Wh1) {
    int r = blockIdx.x;
    int tid = threadIdx.x;
    if (r < 256) {
        __shared__ float row[8256];
        __shared__ float red[8];
        float s = 0.f;
        for (int i = tid; i < 8192; i += 256) {
            float v = Wf[(size_t)r * 8192 + i];
            row[i + (i >> 7)] = v;
            s += v;
        }
        #pragma unroll
        for (int o = 16; o; o >>= 1) s += __shfl_xor_sync(0xffffffffu, s, o);
        if ((tid & 31) == 0) red[tid >> 5] = s;
        __syncthreads();
        if (tid == 0) {
            float t = 0.f;
            #pragma unroll
            for (int j = 0; j < 8; j++) t += red[j];
            g_S[r] = t;
        }
        for (int i = tid; i < 8192; i += 256) {
            int na = i >> 6, e = i & 63;
            int src = e * 128 + na;
            g_Wfbf[(size_t)r * 8192 + i] = __float2bfloat16_rn(row[src + (src >> 7)]);
        }
    } else if (r == 256) {
        for (int i = tid; i < 8192; i += 256) {
            int sel = i >> 12, j = i & 4095;
            int e = j >> 6, hd = j & 63, h = hd >> 4, d = hd & 15;
            const float* W = sel ? Wva : Wve;
            g_Wvbf[i] = __float2bfloat16_rn(W[h * 1024 + e * 16 + d]);
        }
    } else {
        int n = r - 257;   // 0..191
        const float* W = (n < 64) ? (Wb1 + (size_t)n * IN) : (Wh1 + (size_t)(n - 64) * IN);
        uint32_t* d0 = g_WB + (size_t)n * KF;
        uint32_t* d1 = g_WB + (size_t)192 * KF + (size_t)n * KF;
        for (int k = tid; k < IN; k += 256) {
            float x = W[k];
            __nv_bfloat16 hi = __float2bfloat16_rn(x);
            __nv_bfloat16 lo = __float2bfloat16_rn(x - __bfloat162float(hi));
            __nv_bfloat162 p0; p0.x = hi; p0.y = hi;
            __nv_bfloat162 p1; p1.x = lo; p1.y = lo;
            d0[k] = *(uint32_t*)&p0;
            d1[k] = *(uint32_t*)&p1;
        }
    }
}

// =====================================================================
// K1: front GEMM (tensor, split-bf16 exact), obs converted in-register:
//     g_hid[4096,192] = relu(obs @ [Wb1;Wh1]^T + bias)
// =====================================================================
__global__ __launch_bounds__(256) void k_front_tc(const float* __restrict__ obs,
                                                  const float* __restrict__ bb1,
                                                  const float* __restrict__ bh1) {
    __shared__ __align__(128) char sm8[49152];
    const uint32_t sb = smem_u32(sm8);
    const int tid = threadIdx.x, lane = tid & 31, w = tid >> 5;
    const int bm = blockIdx.x * 64, bn = blockIdx.y * 64;
    const int wm = (w & 3) * 16, wn = (w >> 2) * 32;
    // A[2]@0/8192 ; B0[2]@16384/24576 ; B1[2]@32768/40960
    float d[4][4] = {};

    auto stageA = [&](int t, int buf) {
        #pragma unroll
        for (int i = 0; i < 2; i++) {
            int idx = tid + 256 * i;
            int row = idx >> 3, c16 = idx & 7;
            int k0 = t * 32 + c16 * 4;
            float4 v = make_float4(0.f, 0.f, 0.f, 0.f);
            if (k0 < IN) v = *(const float4*)(obs + (size_t)(bm + row) * IN + k0);
            uint32_t p[4];
            {
                float xs[4] = {v.x, v.y, v.z, v.w};
                #pragma unroll
                for (int j = 0; j < 4; j++) {
                    __nv_bfloat16 hi = __float2bfloat16_rn(xs[j]);
                    __nv_bfloat16 lo = __float2bfloat16_rn(xs[j] - __bfloat162float(hi));
                    __nv_bfloat162 pr; pr.x = hi; pr.y = lo;
                    p[j] = *(uint32_t*)&pr;
                }
            }
            *(uint4*)(sm8 + buf * 8192 + SWZ((uint32_t)(row * 128 + c16 * 16))) = *(uint4*)p;
        }
    };
    auto stageB = [&](int t, int buf) {
        #pragma unroll
        for (int i = 0; i < 2; i++) {
            int idx = tid + 256 * i;
            int row = idx >> 3, c16 = idx & 7;
            const uint32_t* s0 = g_WB + (size_t)(bn + row) * KF + t * 32 + c16 * 4;
            uint32_t off = SWZ((uint32_t)(row * 128 + c16 * 16));
            cp16(sb + 16384 + buf * 8192 + off, s0);
            cp16(sb + 32768 + buf * 8192 + off, s0 + (size_t)192 * KF);
        }
        CP_COMMIT();
    };

    stageA(0, 0);
    stageB(0, 0);
    for (int t = 0; t < 65; t++) {
        const int buf = t & 1;
        if (t < 64) {
            stageA(t + 1, buf ^ 1);
            stageB(t + 1, buf ^ 1);
            CP_WAIT(1);
        } else {
            CP_WAIT(0);
        }
        __syncthreads();
        const uint32_t ab = sb + buf * 8192;
        const uint32_t b0b = sb + 16384 + buf * 8192;
        const uint32_t b1b = sb + 32768 + buf * 8192;
        #pragma unroll
        for (int ks = 0; ks < 4; ks++) {
            uint32_t a[4];
            uint32_t byte = (uint32_t)((wm + (lane & 15)) * 128 + (lane >> 4) * 16 + ks * 32);
            LDSM_X4(a[0], a[1], a[2], a[3], ab + SWZ(byte));
            uint32_t b0[4][2], b1[4][2];
            #pragma unroll
            for (int nr = 0; nr < 2; nr++) {
                uint32_t by2 = (uint32_t)((wn + nr * 16 + (lane & 15)) * 128
                                          + (lane >> 4) * 16 + ks * 32);
                uint32_t r0, r1, r2, r3;
                LDSM_X4(r0, r1, r2, r3, b0b + SWZ(by2));
                b0[nr * 2][0] = r0; b0[nr * 2][1] = r2;
                b0[nr * 2 + 1][0] = r1; b0[nr * 2 + 1][1] = r3;
                LDSM_X4(r0, r1, r2, r3, b1b + SWZ(by2));
                b1[nr * 2][0] = r0; b1[nr * 2][1] = r2;
                b1[nr * 2 + 1][0] = r1; b1[nr * 2 + 1][1] = r3;
            }
            #pragma unroll
            for (int nt = 0; nt < 4; nt++) {
                MMA16816(d[nt], a, b0[nt]);
                MMA16816(d[nt], a, b1[nt]);
            }
        }
        __syncthreads();
    }

    #pragma unroll
    for (int half = 0; half < 2; half++) {
        int row = bm + wm + half * 8 + (lane >> 2);
        #pragma unroll
        for (int nt = 0; nt < 4; nt++) {
            int n = bn + wn + nt * 8 + (lane & 3) * 2;
            float bias0 = (n < 64) ? bb1[n] : bh1[n - 64];
            float bias1 = (n + 1 < 64) ? bb1[n + 1] : bh1[n + 1 - 64];
            float v0 = fmaxf(d[nt][half * 2 + 0] + bias0, 0.f);
            float v1 = fmaxf(d[nt][half * 2 + 1] + bias1, 0.f);
            *(float2*)&g_hid[row * 192 + n] = make_float2(v0, v1);
        }
    }
}

// =====================================================================
// K3: fused m-MLPs (stage1 FFMA -> smem bf16, stage2 mma) -> g_q/g_km/g_vm
// =====================================================================
__global__ __launch_bounds__(256) void k_mlp(const float* __restrict__ obs,
                                             const float* __restrict__ Wq1, const float* __restrict__ bq1,
                                             const float* __restrict__ Wq2,
                                             const float* __restrict__ Wkm1, const float* __restrict__ bkm1,
                                             const float* __restrict__ Wkm2,
                                             const float* __restrict__ Wvm1, const float* __restrict__ bvm1,
                                             const float* __restrict__ Wvm2) {
    extern __shared__ __align__(128) char smp[];
    float* msm = (float*)smp;
    float* w1s = (float*)(smp + 12800);
    float* b1s = (float*)(smp + 25600);
    char* h1B = smp + 26112;
    char* w2B = smp + 58880;

    const int tid = threadIdx.x, lane = tid & 31;
    const int bm = blockIdx.x * 128;
    const int mlp = blockIdx.y >> 2, h = blockIdx.y & 3;
    const float* W1 = ((mlp == 0) ? Wq1 : (mlp == 1) ? Wkm1 : Wvm1) + h * HE * MF;
    const float* B1 = ((mlp == 0) ? bq1 : (mlp == 1) ? bkm1 : bvm1) + h * HE;
    const float* W2 = ((mlp == 0) ? Wq2 : (mlp == 1) ? Wkm2 : Wvm2) + h * E * HE;
    float* outp = (mlp == 0) ? g_q : (mlp == 1) ? g_km : g_vm;

    for (int i = tid; i < 128 * 24; i += 256) {
        int r = i / 24, f = i - r * 24;
        int col = (f < 4) ? f : (2032 + f);
        msm[r * 25 + f] = obs[(size_t)(bm + r) * IN + col];
    }
    for (int i = tid; i < 128 * 24; i += 256) {
        int g = i / 24, f = i - g * 24;
        w1s[g * 25 + f] = W1[g * 24 + f];
    }
    if (tid < 128) b1s[tid] = B1[tid];
    for (int i = tid; i < 1024; i += 256) {
        int e = i >> 4, g8 = (i & 15) * 8;
        int kk = g8 >> 6, wi = g8 & 63;
        const float* src = W2 + e * HE + g8;
        float4 v0 = *(const float4*)src;
        float4 v1 = *(const float4*)(src + 4);
        __nv_bfloat162 p[4];
        p[0] = __floats2bfloat162_rn(v0.x, v0.y);
        p[1] = __floats2bfloat162_rn(v0.z, v0.w);
        p[2] = __floats2bfloat162_rn(v1.x, v1.y);
        p[3] = __floats2bfloat162_rn(v1.z, v1.w);
        *(uint4*)(w2B + kk * 8192 + SWZ((uint32_t)(e * 128 + wi * 2))) = *(uint4*)p;
    }
    __syncthreads();

    {
        int r = tid & 127, chalf = tid >> 7;
        float mreg[24];
        #pragma unroll
        for (int f = 0; f < 24; f++) mreg[f] = msm[r * 25 + f];
        char* pan = h1B + chalf * 16384;
        #pragma unroll 4
        for (int c = 0; c < 64; c += 2) {
            int cc = chalf * 64 + c;
            float a0 = b1s[cc], a1 = b1s[cc + 1];
            const float* w0 = w1s + cc * 25;
            #pragma unroll
            for (int f = 0; f < 24; f++) {
                a0 += mreg[f] * w0[f];
                a1 += mreg[f] * w0[25 + f];
            }
            __nv_bfloat162 p = __floats2bfloat162_rn(fmaxf(a0, 0.f), fmaxf(a1, 0.f));
            *(__nv_bfloat162*)(pan + SWZ((uint32_t)(r * 128 + c * 2))) = p;
        }
    }
    __syncthreads();

    {
        int w = tid >> 5;
        int wm = (w & 1) * 64, wn = (w >> 1) * 16;
        uint32_t h1b = smem_u32(h1B);
        uint32_t w2b = smem_u32(w2B);
        float d[4][2][4] = {};
        #pragma unroll
        for (int kk = 0; kk < 2; kk++) {
            uint32_t ab = h1b + kk * 16384;
            uint32_t bb = w2b + kk * 8192;
            #pragma unroll
            for (int ks = 0; ks < 4; ks++) {
                uint32_t bfr[2][2];
                {
                    uint32_t by = (uint32_t)((wn + (lane & 15)) * 128 + (lane >> 4) * 16 + ks * 32);
                    uint32_t r0, r1, r2, r3;
                    LDSM_X4(r0, r1, r2, r3, bb + SWZ(by));
                    bfr[0][0] = r0; bfr[0][1] = r2;
                    bfr[1][0] = r1; bfr[1][1] = r3;
                }
                #pragma unroll
                for (int mt = 0; mt < 4; mt++) {
                    uint32_t a[4];
                    uint32_t by = (uint32_t)((wm + mt * 16 + (lane & 15)) * 128
                                             + (lane >> 4) * 16 + ks * 32);
                    LDSM_X4(a[0], a[1], a[2], a[3], ab + SWZ(by));
                    MMA16816(d[mt][0], a, bfr[0]);
                    MMA16816(d[mt][1], a, bfr[1]);
                }
            }
        }
        #pragma unroll
        for (int mt = 0; mt < 4; mt++)
            #pragma unroll
            for (int half = 0; half < 2; half++) {
                int row = bm + wm + mt * 16 + half * 8 + (lane >> 2);
                #pragma unroll
                for (int nt = 0; nt < 2; nt++) {
                    int e = wn + nt * 8 + (lane & 3) * 2;
                    *(float2*)&outp[(size_t)row * 256 + h * 64 + e] =
                        make_float2(d[mt][nt][half * 2], d[mt][nt][half * 2 + 1]);
                }
            }
    }
}

// =====================================================================
// K4: fused attention (+fold +post_front): per batch:
//  te/ta/l0/b_term/w_head -> logits -> softmax -> Z -> tensor mix -> g_Abf
// =====================================================================
__global__ __launch_bounds__(256) void k_attn(const float* __restrict__ obs,
                                              const float* __restrict__ Wke,
                                              const float* __restrict__ Wka,
                                              const float* __restrict__ Wb2,
                                              const float* __restrict__ bb2,
                                              const float* __restrict__ Wh2,
                                              const float* __restrict__ bh2) {
    __shared__ float ent[2032];
    __shared__ float lg[512];
    __shared__ float u[512];
    __shared__ float vms[256];
    __shared__ float qs[256];
    __shared__ float kms[256];
    __shared__ float tv[128];
    __shared__ float whl[8];
    __shared__ __align__(128) __nv_bfloat16 Zs[128 * 64];
    __shared__ __align__(128) __nv_bfloat16 Wvs[128 * 64];

    int b = blockIdx.x, tid = threadIdx.x;
    char* ZsB = (char*)Zs;
    char* WvsB = (char*)Wvs;

    const float* orow = obs + (size_t)b * IN;
    for (int i = tid; i < 2032; i += 256) ent[i] = orow[4 + i];
    {
        const uint4* wsrc = (const uint4*)g_Wvbf;
        #pragma unroll
        for (int i = tid; i < 1024; i += 256) {
            int row = i >> 3, c = i & 7;
            *(uint4*)(WvsB + SWZ((uint32_t)(row * 128 + c * 16))) = wsrc[i];
        }
    }
    vms[tid] = g_vm[b * 256 + tid];
    qs[tid] = g_q[b * 256 + tid];
    kms[tid] = g_km[b * 256 + tid];
    __syncthreads();

    // ---- phase 2: te/ta (tids 0-127), b_term/w_head (warps 4-7), l0 (warps 0-3)
    if (tid < 128) {
        int h = (tid & 63) >> 4, d = tid & 15;
        const float* Wk = (tid < 64) ? Wke : Wka;
        float s = 0.f;
        #pragma unroll
        for (int e = 0; e < 64; e++) s += qs[h * 64 + e] * Wk[h * 1024 + e * 16 + d];
        tv[tid] = s * 0.125f;
        // l0 per head (warps 0-3)
        int w = tid >> 5, lane = tid & 31;
        float t = qs[w * 64 + lane] * kms[w * 64 + lane] +
                  qs[w * 64 + 32 + lane] * kms[w * 64 + 32 + lane];
        #pragma unroll
        for (int o = 16; o; o >>= 1) t += __shfl_xor_sync(0xffffffffu, t, o);
        if (lane == 0) whl[4 + w] = t * 0.125f;
    } else {
        int w = (tid >> 5) - 4, lane = tid & 31;   // w in 0..3
        const float* hrow = g_hid + b * 192;
        if (w == 0) {
            float s = hrow[lane] * Wb2[lane] + hrow[32 + lane] * Wb2[32 + lane];
            #pragma unroll
            for (int o = 16; o; o >>= 1) s += __shfl_xor_sync(0xffffffffu, s, o);
            if (lane == 0) g_bt[b] = s + bb2[0];
        }
        int h = (w == 0) ? 3 : (w - 1);
        float t = 0.f;
        #pragma unroll
        for (int j = lane; j < 128; j += 32) t += hrow[64 + j] * Wh2[h * 128 + j];
        #pragma unroll
        for (int o = 16; o; o >>= 1) t += __shfl_xor_sync(0xffffffffu, t, o);
        if (lane == 0) whl[h] = fabsf(t + bh2[h]);
    }
    __syncthreads();

    // ---- logits
    for (int i = tid; i < 508; i += 256) {
        int h = i / 127, n = i - h * 127;
        const float* tp = tv + ((n < 64) ? 0 : 64) + h * 16;
        const float* ep = ent + n * 16;
        float s = 0.f;
        #pragma unroll
        for (int d = 0; d < 16; d++) s += ep[d] * tp[d];
        lg[h * 128 + 1 + n] = s;
    }
    if (tid < 4) lg[tid * 128] = whl[4 + tid];
    __syncthreads();

    // ---- softmax (scaled by w_head) -> u
    if (tid < 128) {
        int h = tid >> 5, lane = tid & 31;
        float v0[4], m0 = -3.4e38f;
        #pragma unroll
        for (int j = 0; j < 4; j++) { v0[j] = lg[h * 128 + lane + 32 * j]; m0 = fmaxf(m0, v0[j]); }
        #pragma unroll
        for (int o = 16; o; o >>= 1) m0 = fmaxf(m0, __shfl_xor_sync(0xffffffffu, m0, o));
        float ss = 0.f;
        #pragma unroll
        for (int j = 0; j < 4; j++) { v0[j] = expf(v0[j] - m0); ss += v0[j]; }
        #pragma unroll
        for (int o = 16; o; o >>= 1) ss += __shfl_xor_sync(0xffffffffu, ss, o);
        float sc = whl[tid >> 5] / ss;
        #pragma unroll
        for (int j = 0; j < 4; j++) u[h * 128 + lane + 32 * j] = v0[j] * sc;
    }
    __syncthreads();

    // ---- Z build
    #pragma unroll
    for (int i = tid; i < 8192; i += 256) {
        int n = i >> 6, hd = i & 63;
        float val = 0.f;
        if (n < 127) {
            int h = hd >> 4, d = hd & 15;
            val = u[h * 128 + n + 1] * ent[n * 16 + d];
        }
        *(__nv_bfloat16*)(ZsB + SWZ((uint32_t)(n * 128 + hd * 2))) = __float2bfloat16_rn(val);
    }
    __nv_bfloat16* arow = g_Abf + (size_t)b * KTOT;
    if (tid < 64) {
        float s = 0.f;
        #pragma unroll
        for (int h = 0; h < 4; h++) s += u[h * 128] * vms[h * 64 + tid];
        arow[tid] = __float2bfloat16_rn(s);
    }
    __syncthreads();

    // ---- tensor-core mix
    {
        int w = tid >> 5, lane = tid & 31;
        int sel = w >> 2;
        int mbase = w * 16;
        uint32_t zb = smem_u32(Zs);
        uint32_t wb = smem_u32(Wvs) + (uint32_t)sel * 8192u;
        float d[8][4] = {};
        #pragma unroll
        for (int ks = 0; ks < 4; ks++) {
            uint32_t a[4];
            uint32_t byte = (uint32_t)((mbase + (lane & 15)) * 128 + (lane >> 4) * 16 + ks * 32);
            LDSM_X4(a[0], a[1], a[2], a[3], zb + SWZ(byte));
            uint32_t bfr[8][2];
            #pragma unroll
            for (int nr = 0; nr < 4; nr++) {
                uint32_t byte2 = (uint32_t)((nr * 16 + (lane & 15)) * 128 + (lane >> 4) * 16 + ks * 32);
                uint32_t r0, r1, r2, r3;
                LDSM_X4(r0, r1, r2, r3, wb + SWZ(byte2));
                bfr[nr * 2 + 0][0] = r0; bfr[nr * 2 + 0][1] = r2;
                bfr[nr * 2 + 1][0] = r1; bfr[nr * 2 + 1][1] = r3;
            }
            #pragma unroll
            for (int nt = 0; nt < 8; nt++) MMA16816(d[nt], a, bfr[nt]);
        }
        #pragma unroll
        for (int half = 0; half < 2; half++) {
            int Arow = mbase + half * 8 + (lane >> 2);
            if (Arow < 127) {
                int na = Arow + 1;
                #pragma unroll
                for (int nt = 0; nt < 8; nt++) {
                    int e = nt * 8 + (lane & 3) * 2;
                    __nv_bfloat162 v;
                    v.x = __float2bfloat16_rn(d[nt][half * 2 + 0]);
                    v.y = __float2bfloat16_rn(d[nt][half * 2 + 1]);
                    *(__nv_bfloat162*)(arow + na * 64 + e) = v;
                }
            }
        }
    }
}

// =====================================================================
// K5: bf16 mma GEMM: out[4096,256] = Abf @ Wfbf^T + bt*S + bf
// =====================================================================
__global__ __launch_bounds__(256) void k_final_mma(const float* __restrict__ bfv,
                                                   float* __restrict__ out) {
    __shared__ __align__(128) char sm8[49152];
    const uint32_t sb = smem_u32(sm8);
    const int tid = threadIdx.x, lane = tid & 31, w = tid >> 5;
    const int bm = blockIdx.x * 64, bn = blockIdx.y * 128;
    const int wm = (w & 1) * 32, wn = (w >> 1) * 32;
    const uint32_t Aoff[2] = {0u, 8192u};
    const uint32_t Boff[2] = {16384u, 32768u};

    float d[2][4][4] = {};

    auto loadChunk = [&](int t, int buf) {
        const __nv_bfloat16* Asrc = g_Abf + (size_t)bm * KTOT + (size_t)t * 64;
        #pragma unroll
        for (int i = 0; i < 2; i++) {
            int idx = tid + 256 * i;
            int row = idx >> 3, c = idx & 7;
            cp16(sb + Aoff[buf] + SWZ((uint32_t)(row * 128 + c * 16)),
                 Asrc + (size_t)row * KTOT + c * 8);
        }
        const __nv_bfloat16* Bsrc = g_Wfbf + (size_t)bn * KTOT + (size_t)t * 64;
        #pragma unroll
        for (int i = 0; i < 4; i++) {
            int idx = tid + 256 * i;
            int row = idx >> 3, c = idx & 7;
            cp16(sb + Boff[buf] + SWZ((uint32_t)(row * 128 + c * 16)),
                 Bsrc + (size_t)row * KTOT + c * 8);
        }
        CP_COMMIT();
    };

    loadChunk(0, 0);
    for (int t = 0; t < 128; t++) {
        const int buf = t & 1;
        if (t + 1 < 128) { loadChunk(t + 1, buf ^ 1); CP_WAIT(1); }
        else             { CP_WAIT(0); }
        __syncthreads();

        const uint32_t abase = sb + Aoff[buf];
        const uint32_t bbase = sb + Boff[buf];
        #pragma unroll
        for (int ks = 0; ks < 4; ks++) {
            uint32_t a[2][4], b[4][2];
            #pragma unroll
            for (int mt = 0; mt < 2; mt++) {
                uint32_t byte = (uint32_t)((wm + mt * 16 + (lane & 15)) * 128
                                           + (lane >> 4) * 16 + ks * 32);
                LDSM_X4(a[mt][0], a[mt][1], a[mt][2], a[mt][3], abase + SWZ(byte));
            }
            #pragma unroll
            for (int nr = 0; nr < 2; nr++) {
                uint32_t byte = (uint32_t)((wn + nr * 16 + (lane & 15)) * 128
                                           + (lane >> 4) * 16 + ks * 32);
                uint32_t r0, r1, r2, r3;
                LDSM_X4(r0, r1, r2, r3, bbase + SWZ(byte));
                b[nr * 2 + 0][0] = r0; b[nr * 2 + 0][1] = r2;
                b[nr * 2 + 1][0] = r1; b[nr * 2 + 1][1] = r3;
            }
            #pragma unroll
            for (int mt = 0; mt < 2; mt++)
                #pragma unroll
                for (int nt = 0; nt < 4; nt++)
                    MMA16816(d[mt][nt], a[mt], b[nt]);
        }
        __syncthreads();
    }

    const int nbase = bn + wn + (lane & 3) * 2;
    #pragma unroll
    for (int mt = 0; mt < 2; mt++) {
        #pragma unroll
        for (int half = 0; half < 2; half++) {
            int row = bm + wm + mt * 16 + half * 8 + (lane >> 2);
            float btv = g_bt[row];
            #pragma unroll
            for (int nt = 0; nt < 4; nt++) {
                int col = nbase + nt * 8;
                float v0 = d[mt][nt][half * 2 + 0] + btv * g_S[col]     + bfv[col];
                float v1 = d[mt][nt][half * 2 + 1] + btv * g_S[col + 1] + bfv[col + 1];
                *(float2*)&out[(size_t)row * RNN + col] = make_float2(v0, v1);
            }
        }
    }
}

// =====================================================================
// launch
// =====================================================================
extern "C" void kernel_launch(void* const* d_in, const int* in_sizes, int n_in,
                              void* d_out, int out_size) {
    const float* obs  = (const float*)d_in[0];
    const float* Wq1  = (const float*)d_in[1];
    const float* bq1  = (const float*)d_in[2];
    const float* Wq2  = (const float*)d_in[3];
    const float* Wkm1 = (const float*)d_in[4];
    const float* bkm1 = (const float*)d_in[5];
    const float* Wkm2 = (const float*)d_in[6];
    const float* Wke  = (const float*)d_in[7];
    const float* Wka  = (const float*)d_in[8];
    const float* Wvm1 = (const float*)d_in[9];
    const float* bvm1 = (const float*)d_in[10];
    const float* Wvm2 = (const float*)d_in[11];
    const float* Wve  = (const float*)d_in[12];
    const float* Wva  = (const float*)d_in[13];
    const float* Wb1  = (const float*)d_in[14];
    const float* bb1  = (const float*)d_in[15];
    const float* Wb2  = (const float*)d_in[16];
    const float* bb2  = (const float*)d_in[17];
    const float* Wh1  = (const float*)d_in[18];
    const float* bh1  = (const float*)d_in[19];
    const float* Wh2  = (const float*)d_in[20];
    const float* bh2  = (const float*)d_in[21];
    const float* Wf   = (const float*)d_in[22];
    const float* bf   = (const float*)d_in[23];
    float* out = (float*)d_out;

    const int mlp_smem = 75264;
    cudaFuncSetAttribute(k_mlp, cudaFuncAttributeMaxDynamicSharedMemorySize, mlp_smem);

    k_prep<<<449, 256>>>(Wf, Wve, Wva, Wb1, Wh1);
    k_front_tc<<<dim3(64, 3), 256>>>(obs, bb1, bh1);
    k_mlp<<<dim3(32, 12), 256, mlp_smem>>>(obs, Wq1, bq1, Wq2, Wkm1, bkm1, Wkm2,
                                           Wvm1, bvm1, Wvm2);
    k_attn<<<4096, 256>>>(obs, Wke, Wka, Wb2, bb2, Wh2, bh2);
    k_final_mma<<<dim3(64, 2), 256>>>(bf, out);
}

// round 8
// speedup vs baseline: 8.3552x; 1.0660x over previous
#include <cuda_runtime.h>
#include <cuda_bf16.h>
#include <cstdint>
#include <cstddef>

// ---------------- problem dims ----------------
#define BS 4096
#define IN 2056
#define MF 24
#define H 4
#define HE 128
#define E 64
#define NA 128
#define RNN 256
#define KTOT 8192         // E*NA
#define KF 2080           // front K in uint32 (bf16x2 pairs), 65 chunks of 32

// ---------------- scratch (device globals; no allocs allowed) ----------------
__device__ float g_hid[BS * 192];
__device__ float g_bt[BS];
__device__ float g_q[BS * H * E];
__device__ float g_km[BS * H * E];
__device__ float g_vm[BS * H * E];
__device__ float g_S[RNN];
// A for final GEMM, layout [b][na*64+e]  (PERMUTED k-index)
__device__ __align__(16) __nv_bfloat16 g_Abf[(size_t)BS * KTOT];
// Wf in bf16, same permuted layout
__device__ __align__(16) __nv_bfloat16 g_Wfbf[(size_t)RNN * KTOT];
// flattened value weights: [sel][e][h*16+d]
__device__ __align__(16) __nv_bfloat16 g_Wvbf[2 * 64 * 64];
// front weights [pass 0=hi,1=lo][192][KF] uint32 (pad cols stay zero)
__device__ __align__(16) uint32_t g_WB[(size_t)2 * 192 * KF];

// ---------------- PTX helpers ----------------
__device__ __forceinline__ uint32_t smem_u32(const void* p) {
    uint32_t a;
    asm("{ .reg .u64 t; cvta.to.shared.u64 t, %1; cvt.u32.u64 %0, t; }" : "=r"(a) : "l"(p));
    return a;
}
__device__ __forceinline__ void cp16(uint32_t dst, const void* src) {
    asm volatile("cp.async.cg.shared.global [%0], [%1], 16;" :: "r"(dst), "l"(src) : "memory");
}
#define CP_COMMIT() asm volatile("cp.async.commit_group;" ::: "memory")
#define CP_WAIT(n)  asm volatile("cp.async.wait_group %0;" :: "n"(n) : "memory")

#define LDSM_X4(r0, r1, r2, r3, addr) \
    asm volatile("ldmatrix.sync.aligned.m8n8.x4.shared.b16 {%0,%1,%2,%3}, [%4];" \
                 : "=r"(r0), "=r"(r1), "=r"(r2), "=r"(r3) : "r"(addr))

#define MMA16816(d, a, b) \
    asm volatile("mma.sync.aligned.m16n8k16.row.col.f32.bf16.bf16.f32 " \
                 "{%0,%1,%2,%3}, {%4,%5,%6,%7}, {%8,%9}, {%0,%1,%2,%3};" \
                 : "+f"((d)[0]), "+f"((d)[1]), "+f"((d)[2]), "+f"((d)[3]) \
                 : "r"((a)[0]), "r"((a)[1]), "r"((a)[2]), "r"((a)[3]), \
                   "r"((b)[0]), "r"((b)[1]))

#define SWZ(x) ((x) ^ (((x) >> 3) & 0x70))

__device__ __forceinline__ uint32_t packbf2(float x, float y) {
    __nv_bfloat162 p = __floats2bfloat162_rn(x, y);
    return *(uint32_t*)&p;
}

// =====================================================================
// K0: prep — blocks 0..255: Wf row -> permuted bf16 + S[r]
//           block 256: flatten Wve/Wva
//           blocks 257..448: front weights hi/lo
// =====================================================================
__global__ __launch_bounds__(256) void k_prep(const float* __restrict__ Wf,
                                              const float* __restrict__ Wve,
                                              const float* __restrict__ Wva,
                                              const float* __restrict__ Wb1,
                                              const float* __restrict__ Wh1) {
    int r = blockIdx.x;
    int tid = threadIdx.x;
    if (r < 256) {
        __shared__ float row[8256];
        __shared__ float red[8];
        float s = 0.f;
        for (int i = tid; i < 8192; i += 256) {
            float v = Wf[(size_t)r * 8192 + i];
            row[i + (i >> 7)] = v;
            s += v;
        }
        #pragma unroll
        for (int o = 16; o; o >>= 1) s += __shfl_xor_sync(0xffffffffu, s, o);
        if ((tid & 31) == 0) red[tid >> 5] = s;
        __syncthreads();
        if (tid == 0) {
            float t = 0.f;
            #pragma unroll
            for (int j = 0; j < 8; j++) t += red[j];
            g_S[r] = t;
        }
        for (int i = tid; i < 8192; i += 256) {
            int na = i >> 6, e = i & 63;
            int src = e * 128 + na;
            g_Wfbf[(size_t)r * 8192 + i] = __float2bfloat16_rn(row[src + (src >> 7)]);
        }
    } else if (r == 256) {
        for (int i = tid; i < 8192; i += 256) {
            int sel = i >> 12, j = i & 4095;
            int e = j >> 6, hd = j & 63, h = hd >> 4, d = hd & 15;
            const float* W = sel ? Wva : Wve;
            g_Wvbf[i] = __float2bfloat16_rn(W[h * 1024 + e * 16 + d]);
        }
    } else {
        int n = r - 257;   // 0..191
        const float* W = (n < 64) ? (Wb1 + (size_t)n * IN) : (Wh1 + (size_t)(n - 64) * IN);
        uint32_t* d0 = g_WB + (size_t)n * KF;
        uint32_t* d1 = g_WB + (size_t)192 * KF + (size_t)n * KF;
        for (int k = tid; k < IN; k += 256) {
            float x = W[k];
            __nv_bfloat16 hi = __float2bfloat16_rn(x);
            __nv_bfloat16 lo = __float2bfloat16_rn(x - __bfloat162float(hi));
            __nv_bfloat162 p0; p0.x = hi; p0.y = hi;
            __nv_bfloat162 p1; p1.x = lo; p1.y = lo;
            d0[k] = *(uint32_t*)&p0;
            d1[k] = *(uint32_t*)&p1;
        }
    }
}

// =====================================================================
// K1: front GEMM (tensor, split-bf16 exact), obs converted in-register:
//     g_hid[4096,192] = relu(obs @ [Wb1;Wh1]^T + bias)
// =====================================================================
__global__ __launch_bounds__(256) void k_front_tc(const float* __restrict__ obs,
                                                  const float* __restrict__ bb1,
                                                  const float* __restrict__ bh1) {
    __shared__ __align__(128) char sm8[49152];
    const uint32_t sb = smem_u32(sm8);
    const int tid = threadIdx.x, lane = tid & 31, w = tid >> 5;
    const int bm = blockIdx.x * 64, bn = blockIdx.y * 64;
    const int wm = (w & 3) * 16, wn = (w >> 2) * 32;
    float d[4][4] = {};

    auto stageA = [&](int t, int buf) {
        #pragma unroll
        for (int i = 0; i < 2; i++) {
            int idx = tid + 256 * i;
            int row = idx >> 3, c16 = idx & 7;
            int k0 = t * 32 + c16 * 4;
            float4 v = make_float4(0.f, 0.f, 0.f, 0.f);
            if (k0 < IN) v = *(const float4*)(obs + (size_t)(bm + row) * IN + k0);
            uint32_t p[4];
            {
                float xs[4] = {v.x, v.y, v.z, v.w};
                #pragma unroll
                for (int j = 0; j < 4; j++) {
                    __nv_bfloat16 hi = __float2bfloat16_rn(xs[j]);
                    __nv_bfloat16 lo = __float2bfloat16_rn(xs[j] - __bfloat162float(hi));
                    __nv_bfloat162 pr; pr.x = hi; pr.y = lo;
                    p[j] = *(uint32_t*)&pr;
                }
            }
            *(uint4*)(sm8 + buf * 8192 + SWZ((uint32_t)(row * 128 + c16 * 16))) = *(uint4*)p;
        }
    };
    auto stageB = [&](int t, int buf) {
        #pragma unroll
        for (int i = 0; i < 2; i++) {
            int idx = tid + 256 * i;
            int row = idx >> 3, c16 = idx & 7;
            const uint32_t* s0 = g_WB + (size_t)(bn + row) * KF + t * 32 + c16 * 4;
            uint32_t off = SWZ((uint32_t)(row * 128 + c16 * 16));
            cp16(sb + 16384 + buf * 8192 + off, s0);
            cp16(sb + 32768 + buf * 8192 + off, s0 + (size_t)192 * KF);
        }
        CP_COMMIT();
    };

    stageA(0, 0);
    stageB(0, 0);
    for (int t = 0; t < 65; t++) {
        const int buf = t & 1;
        if (t < 64) {
            stageA(t + 1, buf ^ 1);
            stageB(t + 1, buf ^ 1);
            CP_WAIT(1);
        } else {
            CP_WAIT(0);
        }
        __syncthreads();
        const uint32_t ab = sb + buf * 8192;
        const uint32_t b0b = sb + 16384 + buf * 8192;
        const uint32_t b1b = sb + 32768 + buf * 8192;
        #pragma unroll
        for (int ks = 0; ks < 4; ks++) {
            uint32_t a[4];
            uint32_t byte = (uint32_t)((wm + (lane & 15)) * 128 + (lane >> 4) * 16 + ks * 32);
            LDSM_X4(a[0], a[1], a[2], a[3], ab + SWZ(byte));
            uint32_t b0[4][2], b1[4][2];
            #pragma unroll
            for (int nr = 0; nr < 2; nr++) {
                uint32_t by2 = (uint32_t)((wn + nr * 16 + (lane & 15)) * 128
                                          + (lane >> 4) * 16 + ks * 32);
                uint32_t r0, r1, r2, r3;
                LDSM_X4(r0, r1, r2, r3, b0b + SWZ(by2));
                b0[nr * 2][0] = r0; b0[nr * 2][1] = r2;
                b0[nr * 2 + 1][0] = r1; b0[nr * 2 + 1][1] = r3;
                LDSM_X4(r0, r1, r2, r3, b1b + SWZ(by2));
                b1[nr * 2][0] = r0; b1[nr * 2][1] = r2;
                b1[nr * 2 + 1][0] = r1; b1[nr * 2 + 1][1] = r3;
            }
            #pragma unroll
            for (int nt = 0; nt < 4; nt++) {
                MMA16816(d[nt], a, b0[nt]);
                MMA16816(d[nt], a, b1[nt]);
            }
        }
        __syncthreads();
    }

    #pragma unroll
    for (int half = 0; half < 2; half++) {
        int row = bm + wm + half * 8 + (lane >> 2);
        #pragma unroll
        for (int nt = 0; nt < 4; nt++) {
            int n = bn + wn + nt * 8 + (lane & 3) * 2;
            float bias0 = (n < 64) ? bb1[n] : bh1[n - 64];
            float bias1 = (n + 1 < 64) ? bb1[n + 1] : bh1[n + 1 - 64];
            float v0 = fmaxf(d[nt][half * 2 + 0] + bias0, 0.f);
            float v1 = fmaxf(d[nt][half * 2 + 1] + bias1, 0.f);
            *(float2*)&g_hid[row * 192 + n] = make_float2(v0, v1);
        }
    }
}

// =====================================================================
// K3: fused m-MLPs (stage1 FFMA -> smem bf16, stage2 mma) -> g_q/g_km/g_vm
// =====================================================================
__global__ __launch_bounds__(256) void k_mlp(const float* __restrict__ obs,
                                             const float* __restrict__ Wq1, const float* __restrict__ bq1,
                                             const float* __restrict__ Wq2,
                                             const float* __restrict__ Wkm1, const float* __restrict__ bkm1,
                                             const float* __restrict__ Wkm2,
                                             const float* __restrict__ Wvm1, const float* __restrict__ bvm1,
                                             const float* __restrict__ Wvm2) {
    extern __shared__ __align__(128) char smp[];
    float* msm = (float*)smp;
    float* w1s = (float*)(smp + 12800);
    float* b1s = (float*)(smp + 25600);
    char* h1B = smp + 26112;
    char* w2B = smp + 58880;

    const int tid = threadIdx.x, lane = tid & 31;
    const int bm = blockIdx.x * 128;
    const int mlp = blockIdx.y >> 2, h = blockIdx.y & 3;
    const float* W1 = ((mlp == 0) ? Wq1 : (mlp == 1) ? Wkm1 : Wvm1) + h * HE * MF;
    const float* B1 = ((mlp == 0) ? bq1 : (mlp == 1) ? bkm1 : bvm1) + h * HE;
    const float* W2 = ((mlp == 0) ? Wq2 : (mlp == 1) ? Wkm2 : Wvm2) + h * E * HE;
    float* outp = (mlp == 0) ? g_q : (mlp == 1) ? g_km : g_vm;

    for (int i = tid; i < 128 * 24; i += 256) {
        int r = i / 24, f = i - r * 24;
        int col = (f < 4) ? f : (2032 + f);
        msm[r * 25 + f] = obs[(size_t)(bm + r) * IN + col];
    }
    for (int i = tid; i < 128 * 24; i += 256) {
        int g = i / 24, f = i - g * 24;
        w1s[g * 25 + f] = W1[g * 24 + f];
    }
    if (tid < 128) b1s[tid] = B1[tid];
    for (int i = tid; i < 1024; i += 256) {
        int e = i >> 4, g8 = (i & 15) * 8;
        int kk = g8 >> 6, wi = g8 & 63;
        const float* src = W2 + e * HE + g8;
        float4 v0 = *(const float4*)src;
        float4 v1 = *(const float4*)(src + 4);
        __nv_bfloat162 p[4];
        p[0] = __floats2bfloat162_rn(v0.x, v0.y);
        p[1] = __floats2bfloat162_rn(v0.z, v0.w);
        p[2] = __floats2bfloat162_rn(v1.x, v1.y);
        p[3] = __floats2bfloat162_rn(v1.z, v1.w);
        *(uint4*)(w2B + kk * 8192 + SWZ((uint32_t)(e * 128 + wi * 2))) = *(uint4*)p;
    }
    __syncthreads();

    {
        int r = tid & 127, chalf = tid >> 7;
        float mreg[24];
        #pragma unroll
        for (int f = 0; f < 24; f++) mreg[f] = msm[r * 25 + f];
        char* pan = h1B + chalf * 16384;
        #pragma unroll 4
        for (int c = 0; c < 64; c += 2) {
            int cc = chalf * 64 + c;
            float a0 = b1s[cc], a1 = b1s[cc + 1];
            const float* w0 = w1s + cc * 25;
            #pragma unroll
            for (int f = 0; f < 24; f++) {
                a0 += mreg[f] * w0[f];
                a1 += mreg[f] * w0[25 + f];
            }
            __nv_bfloat162 p = __floats2bfloat162_rn(fmaxf(a0, 0.f), fmaxf(a1, 0.f));
            *(__nv_bfloat162*)(pan + SWZ((uint32_t)(r * 128 + c * 2))) = p;
        }
    }
    __syncthreads();

    {
        int w = tid >> 5;
        int wm = (w & 1) * 64, wn = (w >> 1) * 16;
        uint32_t h1b = smem_u32(h1B);
        uint32_t w2b = smem_u32(w2B);
        float d[4][2][4] = {};
        #pragma unroll
        for (int kk = 0; kk < 2; kk++) {
            uint32_t ab = h1b + kk * 16384;
            uint32_t bb = w2b + kk * 8192;
            #pragma unroll
            for (int ks = 0; ks < 4; ks++) {
                uint32_t bfr[2][2];
                {
                    uint32_t by = (uint32_t)((wn + (lane & 15)) * 128 + (lane >> 4) * 16 + ks * 32);
                    uint32_t r0, r1, r2, r3;
                    LDSM_X4(r0, r1, r2, r3, bb + SWZ(by));
                    bfr[0][0] = r0; bfr[0][1] = r2;
                    bfr[1][0] = r1; bfr[1][1] = r3;
                }
                #pragma unroll
                for (int mt = 0; mt < 4; mt++) {
                    uint32_t a[4];
                    uint32_t by = (uint32_t)((wm + mt * 16 + (lane & 15)) * 128
                                             + (lane >> 4) * 16 + ks * 32);
                    LDSM_X4(a[0], a[1], a[2], a[3], ab + SWZ(by));
                    MMA16816(d[mt][0], a, bfr[0]);
                    MMA16816(d[mt][1], a, bfr[1]);
                }
            }
        }
        #pragma unroll
        for (int mt = 0; mt < 4; mt++)
            #pragma unroll
            for (int half = 0; half < 2; half++) {
                int row = bm + wm + mt * 16 + half * 8 + (lane >> 2);
                #pragma unroll
                for (int nt = 0; nt < 2; nt++) {
                    int e = wn + nt * 8 + (lane & 3) * 2;
                    *(float2*)&outp[(size_t)row * 256 + h * 64 + e] =
                        make_float2(d[mt][nt][half * 2], d[mt][nt][half * 2 + 1]);
                }
            }
    }
}

// =====================================================================
// K4: fused attention: te/ta/l0/b_term/w_head -> logits -> softmax ->
//     register-built A-fragments (Z never materialized) -> tensor mix -> g_Abf
// =====================================================================
__global__ __launch_bounds__(256) void k_attn(const float* __restrict__ obs,
                                              const float* __restrict__ Wke,
                                              const float* __restrict__ Wka,
                                              const float* __restrict__ Wb2,
                                              const float* __restrict__ bb2,
                                              const float* __restrict__ Wh2,
                                              const float* __restrict__ bh2) {
    __shared__ float ent[2048];        // padded (rows 127 zeros)
    __shared__ float lg[512];
    __shared__ float u[512];
    __shared__ float vms[256];
    __shared__ float qs[256];
    __shared__ float kms[256];
    __shared__ float tv[128];
    __shared__ float whl[8];
    __shared__ __align__(128) __nv_bfloat16 Wvs[128 * 64];

    int b = blockIdx.x, tid = threadIdx.x;
    char* WvsB = (char*)Wvs;

    const float* orow = obs + (size_t)b * IN;
    // vectorized ent load: orow+4 is 16B-aligned; 2032 floats = 508 float4
    {
        const float4* src4 = (const float4*)(orow + 4);
        #pragma unroll
        for (int i = tid; i < 508; i += 256) ((float4*)ent)[i] = src4[i];
        if (tid < 16) ent[2032 + tid] = 0.f;
    }
    {
        const uint4* wsrc = (const uint4*)g_Wvbf;
        #pragma unroll
        for (int i = tid; i < 1024; i += 256) {
            int row = i >> 3, c = i & 7;
            *(uint4*)(WvsB + SWZ((uint32_t)(row * 128 + c * 16))) = wsrc[i];
        }
    }
    vms[tid] = g_vm[b * 256 + tid];
    qs[tid] = g_q[b * 256 + tid];
    kms[tid] = g_km[b * 256 + tid];
    __syncthreads();

    // ---- te/ta (tids 0-127) + l0 (warps 0-3); b_term/w_head (warps 4-7)
    if (tid < 128) {
        int h = (tid & 63) >> 4, d = tid & 15;
        const float* Wk = (tid < 64) ? Wke : Wka;
        float s = 0.f;
        #pragma unroll
        for (int e = 0; e < 64; e++) s += qs[h * 64 + e] * Wk[h * 1024 + e * 16 + d];
        tv[tid] = s * 0.125f;
        int w = tid >> 5, lane = tid & 31;
        float t = qs[w * 64 + lane] * kms[w * 64 + lane] +
                  qs[w * 64 + 32 + lane] * kms[w * 64 + 32 + lane];
        #pragma unroll
        for (int o = 16; o; o >>= 1) t += __shfl_xor_sync(0xffffffffu, t, o);
        if (lane == 0) whl[4 + w] = t * 0.125f;
    } else {
        int w = (tid >> 5) - 4, lane = tid & 31;
        const float* hrow = g_hid + b * 192;
        if (w == 0) {
            float s = hrow[lane] * Wb2[lane] + hrow[32 + lane] * Wb2[32 + lane];
            #pragma unroll
            for (int o = 16; o; o >>= 1) s += __shfl_xor_sync(0xffffffffu, s, o);
            if (lane == 0) g_bt[b] = s + bb2[0];
        }
        int h = (w == 0) ? 3 : (w - 1);
        float t = 0.f;
        #pragma unroll
        for (int j = lane; j < 128; j += 32) t += hrow[64 + j] * Wh2[h * 128 + j];
        #pragma unroll
        for (int o = 16; o; o >>= 1) t += __shfl_xor_sync(0xffffffffu, t, o);
        if (lane == 0) whl[h] = fabsf(t + bh2[h]);
    }
    __syncthreads();

    // ---- logits
    for (int i = tid; i < 508; i += 256) {
        int h = i / 127, n = i - h * 127;
        const float* tp = tv + ((n < 64) ? 0 : 64) + h * 16;
        const float* ep = ent + n * 16;
        float s = 0.f;
        #pragma unroll
        for (int d = 0; d < 16; d++) s += ep[d] * tp[d];
        lg[h * 128 + 1 + n] = s;
    }
    if (tid < 4) lg[tid * 128] = whl[4 + tid];
    __syncthreads();

    // ---- softmax (scaled by w_head) -> u
    if (tid < 128) {
        int h = tid >> 5, lane = tid & 31;
        float v0[4], m0 = -3.4e38f;
        #pragma unroll
        for (int j = 0; j < 4; j++) { v0[j] = lg[h * 128 + lane + 32 * j]; m0 = fmaxf(m0, v0[j]); }
        #pragma unroll
        for (int o = 16; o; o >>= 1) m0 = fmaxf(m0, __shfl_xor_sync(0xffffffffu, m0, o));
        float ss = 0.f;
        #pragma unroll
        for (int j = 0; j < 4; j++) { v0[j] = expf(v0[j] - m0); ss += v0[j]; }
        #pragma unroll
        for (int o = 16; o; o >>= 1) ss += __shfl_xor_sync(0xffffffffu, ss, o);
        float sc = whl[h] / ss;
        #pragma unroll
        for (int j = 0; j < 4; j++) u[h * 128 + lane + 32 * j] = v0[j] * sc;
    }
    __syncthreads();

    __nv_bfloat16* arow = g_Abf + (size_t)b * KTOT;
    if (tid < 64) {
        float s = 0.f;
        #pragma unroll
        for (int h = 0; h < 4; h++) s += u[h * 128] * vms[h * 64 + tid];
        arow[tid] = __float2bfloat16_rn(s);
    }

    // ---- tensor-core mix: A-fragments built in registers
    {
        int w = tid >> 5, lane = tid & 31;
        int sel = w >> 2;
        int mbase = w * 16;
        int r = mbase + (lane >> 2);   // Z row for a0/a2; r+8 for a1/a3
        int c0 = (lane & 3) * 2;       // d base
        uint32_t wb = smem_u32(Wvs) + (uint32_t)sel * 8192u;

        float2 eA = *(float2*)&ent[r * 16 + c0];
        float2 eB = *(float2*)&ent[r * 16 + c0 + 8];
        float2 eC = *(float2*)&ent[(r + 8) * 16 + c0];
        float2 eD = *(float2*)&ent[(r + 8) * 16 + c0 + 8];

        float d[8][4] = {};
        #pragma unroll
        for (int ks = 0; ks < 4; ks++) {
            float ul = (r < 127)     ? u[ks * 128 + r + 1] : 0.f;
            float uh = (r + 8 < 127) ? u[ks * 128 + r + 9] : 0.f;
            uint32_t a[4];
            a[0] = packbf2(ul * eA.x, ul * eA.y);
            a[1] = packbf2(uh * eC.x, uh * eC.y);
            a[2] = packbf2(ul * eB.x, ul * eB.y);
            a[3] = packbf2(uh * eD.x, uh * eD.y);
            uint32_t bfr[8][2];
            #pragma unroll
            for (int nr = 0; nr < 4; nr++) {
                uint32_t byte2 = (uint32_t)((nr * 16 + (lane & 15)) * 128 + (lane >> 4) * 16 + ks * 32);
                uint32_t r0, r1, r2, r3;
                LDSM_X4(r0, r1, r2, r3, wb + SWZ(byte2));
                bfr[nr * 2 + 0][0] = r0; bfr[nr * 2 + 0][1] = r2;
                bfr[nr * 2 + 1][0] = r1; bfr[nr * 2 + 1][1] = r3;
            }
            #pragma unroll
            for (int nt = 0; nt < 8; nt++) MMA16816(d[nt], a, bfr[nt]);
        }
        #pragma unroll
        for (int half = 0; half < 2; half++) {
            int Arow = mbase + half * 8 + (lane >> 2);
            if (Arow < 127) {
                int na = Arow + 1;
                #pragma unroll
                for (int nt = 0; nt < 8; nt++) {
                    int e = nt * 8 + (lane & 3) * 2;
                    __nv_bfloat162 v;
                    v.x = __float2bfloat16_rn(d[nt][half * 2 + 0]);
                    v.y = __float2bfloat16_rn(d[nt][half * 2 + 1]);
                    *(__nv_bfloat162*)(arow + na * 64 + e) = v;
                }
            }
        }
    }
}

// =====================================================================
// K5: bf16 mma GEMM: out[4096,256] = Abf @ Wfbf^T + bt*S + bf
// =====================================================================
__global__ __launch_bounds__(256) void k_final_mma(const float* __restrict__ bfv,
                                                   float* __restrict__ out) {
    __shared__ __align__(128) char sm8[49152];
    const uint32_t sb = smem_u32(sm8);
    const int tid = threadIdx.x, lane = tid & 31, w = tid >> 5;
    const int bm = blockIdx.x * 64, bn = blockIdx.y * 128;
    const int wm = (w & 1) * 32, wn = (w >> 1) * 32;
    const uint32_t Aoff[2] = {0u, 8192u};
    const uint32_t Boff[2] = {16384u, 32768u};

    float d[2][4][4] = {};

    auto loadChunk = [&](int t, int buf) {
        const __nv_bfloat16* Asrc = g_Abf + (size_t)bm * KTOT + (size_t)t * 64;
        #pragma unroll
        for (int i = 0; i < 2; i++) {
            int idx = tid + 256 * i;
            int row = idx >> 3, c = idx & 7;
            cp16(sb + Aoff[buf] + SWZ((uint32_t)(row * 128 + c * 16)),
                 Asrc + (size_t)row * KTOT + c * 8);
        }
        const __nv_bfloat16* Bsrc = g_Wfbf + (size_t)bn * KTOT + (size_t)t * 64;
        #pragma unroll
        for (int i = 0; i < 4; i++) {
            int idx = tid + 256 * i;
            int row = idx >> 3, c = idx & 7;
            cp16(sb + Boff[buf] + SWZ((uint32_t)(row * 128 + c * 16)),
                 Bsrc + (size_t)row * KTOT + c * 8);
        }
        CP_COMMIT();
    };

    loadChunk(0, 0);
    for (int t = 0; t < 128; t++) {
        const int buf = t & 1;
        if (t + 1 < 128) { loadChunk(t + 1, buf ^ 1); CP_WAIT(1); }
        else             { CP_WAIT(0); }
        __syncthreads();

        const uint32_t abase = sb + Aoff[buf];
        const uint32_t bbase = sb + Boff[buf];
        #pragma unroll
        for (int ks = 0; ks < 4; ks++) {
            uint32_t a[2][4], b[4][2];
            #pragma unroll
            for (int mt = 0; mt < 2; mt++) {
                uint32_t byte = (uint32_t)((wm + mt * 16 + (lane & 15)) * 128
                                           + (lane >> 4) * 16 + ks * 32);
                LDSM_X4(a[mt][0], a[mt][1], a[mt][2], a[mt][3], abase + SWZ(byte));
            }
            #pragma unroll
            for (int nr = 0; nr < 2; nr++) {
                uint32_t byte = (uint32_t)((wn + nr * 16 + (lane & 15)) * 128
                                           + (lane >> 4) * 16 + ks * 32);
                uint32_t r0, r1, r2, r3;
                LDSM_X4(r0, r1, r2, r3, bbase + SWZ(byte));
                b[nr * 2 + 0][0] = r0; b[nr * 2 + 0][1] = r2;
                b[nr * 2 + 1][0] = r1; b[nr * 2 + 1][1] = r3;
            }
            #pragma unroll
            for (int mt = 0; mt < 2; mt++)
                #pragma unroll
                for (int nt = 0; nt < 4; nt++)
                    MMA16816(d[mt][nt], a[mt], b[nt]);
        }
        __syncthreads();
    }

    const int nbase = bn + wn + (lane & 3) * 2;
    #pragma unroll
    for (int mt = 0; mt < 2; mt++) {
        #pragma unroll
        for (int half = 0; half < 2; half++) {
            int row = bm + wm + mt * 16 + half * 8 + (lane >> 2);
            float btv = g_bt[row];
            #pragma unroll
            for (int nt = 0; nt < 4; nt++) {
                int col = nbase + nt * 8;
                float v0 = d[mt][nt][half * 2 + 0] + btv * g_S[col]     + bfv[col];
                float v1 = d[mt][nt][half * 2 + 1] + btv * g_S[col + 1] + bfv[col + 1];
                *(float2*)&out[(size_t)row * RNN + col] = make_float2(v0, v1);
            }
        }
    }
}

// =====================================================================
// launch
// =====================================================================
extern "C" void kernel_launch(void* const* d_in, const int* in_sizes, int n_in,
                              void* d_out, int out_size) {
    const float* obs  = (const float*)d_in[0];
    const float* Wq1  = (const float*)d_in[1];
    const float* bq1  = (const float*)d_in[2];
    const float* Wq2  = (const float*)d_in[3];
    const float* Wkm1 = (const float*)d_in[4];
    const float* bkm1 = (const float*)d_in[5];
    const float* Wkm2 = (const float*)d_in[6];
    const float* Wke  = (const float*)d_in[7];
    const float* Wka  = (const float*)d_in[8];
    const float* Wvm1 = (const float*)d_in[9];
    const float* bvm1 = (const float*)d_in[10];
    const float* Wvm2 = (const float*)d_in[11];
    const float* Wve  = (const float*)d_in[12];
    const float* Wva  = (const float*)d_in[13];
    const float* Wb1  = (const float*)d_in[14];
    const float* bb1  = (const float*)d_in[15];
    const float* Wb2  = (const float*)d_in[16];
    const float* bb2  = (const float*)d_in[17];
    const float* Wh1  = (const float*)d_in[18];
    const float* bh1  = (const float*)d_in[19];
    const float* Wh2  = (const float*)d_in[20];
    const float* bh2  = (const float*)d_in[21];
    const float* Wf   = (const float*)d_in[22];
    const float* bf   = (const float*)d_in[23];
    float* out = (float*)d_out;

    const int mlp_smem = 75264;
    cudaFuncSetAttribute(k_mlp, cudaFuncAttributeMaxDynamicSharedMemorySize, mlp_smem);

    k_prep<<<449, 256>>>(Wf, Wve, Wva, Wb1, Wh1);
    k_front_tc<<<dim3(64, 3), 256>>>(obs, bb1, bh1);
    k_mlp<<<dim3(32, 12), 256, mlp_smem>>>(obs, Wq1, bq1, Wq2, Wkm1, bkm1, Wkm2,
                                           Wvm1, bvm1, Wvm2);
    k_attn<<<4096, 256>>>(obs, Wke, Wka, Wb2, bb2, Wh2, bh2);
    k_final_mma<<<dim3(64, 2), 256>>>(bf, out);
}